// round 12
// baseline (speedup 1.0000x reference)
#include <cuda_runtime.h>
#include <cuda_fp16.h>
#include <math.h>
#include <stdint.h>

#define NB   256
#define DIN  5000
#define NH1  2048
#define NH2  1024
#define NISO 100000
#define NG   25000

// ---------------- scratch (static device arrays; allocation-free) ----------------
__device__ float  g_h1[NB * NH1];
__device__ float  g_h2[NB * NH2];
__device__ __half g_h2h[NB * NH2];
__device__ float  g_denom2[NG * NB];   // [gene][batch]
__device__ float  g_denomT[NB * NG];   // [batch][gene]

// ---------------- helpers ----------------
__device__ __forceinline__ void cp16(void* s, const void* g, bool pred) {
    uint32_t sa = (uint32_t)__cvta_generic_to_shared(s);
    int sz = pred ? 16 : 0;
    asm volatile("cp.async.cg.shared.global [%0], [%1], 16, %2;\n"
                 :: "r"(sa), "l"(g), "r"(sz) : "memory");
}

__device__ __forceinline__ void mma_f16(float* c, const uint32_t* a, const uint32_t* b) {
    asm volatile(
        "mma.sync.aligned.m16n8k16.row.col.f32.f16.f16.f32 "
        "{%0,%1,%2,%3}, {%4,%5,%6,%7}, {%8,%9}, {%0,%1,%2,%3};\n"
        : "+f"(c[0]), "+f"(c[1]), "+f"(c[2]), "+f"(c[3])
        : "r"(a[0]), "r"(a[1]), "r"(a[2]), "r"(a[3]), "r"(b[0]), "r"(b[1]));
}

// pack two f32 -> f16x2 register {lo=first, hi=second}
__device__ __forceinline__ uint32_t pack_f16(float lo, float hi) {
    uint32_t r;
    asm("cvt.rn.f16x2.f32 %0, %1, %2;" : "=r"(r) : "f"(hi), "f"(lo));
    return r;
}

// ================= GEMM3: hybrid HMMA(128 cols) + FFMA(16 cols), BM=256, BN=144, BK=32 ===========
// A = g_h2h fp16; B = W3 fp32 (smem f32; tensor path converts, FFMA path reads native f32).
// Epilogue: bias + exp -> smem staging -> red.global.add.v4 denom + coalesced stores.
__global__ void __launch_bounds__(512, 1)
gemm3_hyb_kernel(const __half* __restrict__ A, const float* __restrict__ W,
                 const float* __restrict__ bias, const int* __restrict__ idx,
                 float* __restrict__ out, float* __restrict__ denom2)
{
    constexpr int S    = 4;
    constexpr int BK   = 32;
    constexpr int BN   = 144;        // 128 tensor + 16 ffma
    constexpr int TK   = NH2 / BK;   // 32
    constexpr int AP   = 40;         // halfs per A row (32 + 8 pad)
    constexpr int BNP  = BN + 4;     // 148 floats per B row
    constexpr int ASTG = 256 * AP;   // halfs per A stage (20480 B)
    constexpr int BSTG = BK * BNP;   // floats per B stage (18944 B)
    constexpr int BCH  = BK * BN / 4; // 1152 chunks of 16B

    extern __shared__ char sm3[];
    __half* sA  = (__half*)sm3;
    float*  sB  = (float*)(sm3 + S * ASTG * 2);
    float*  sEp = (float*)sm3;       // epilogue reuse: 256 x 148 floats (151552 B)

    const int tid  = threadIdx.x;
    const int warp = tid >> 5;
    const int lane = tid & 31;
    const int g    = lane >> 2;
    const int tig  = lane & 3;
    const int wm   = (warp >> 2) * 64;   // 0,64,128,192
    const int wn   = (warp & 3) * 32;    // 0,32,64,96
    const int bn   = blockIdx.x * BN;

    // FFMA-path assignment: colpair cp (cols 128+2cp, 129+2cp), rows rg + 64*j
    const int cp = tid & 7;
    const int rg = tid >> 3;             // 0..63

    float acc[4][4][4];
#pragma unroll
    for (int i = 0; i < 4; ++i)
#pragma unroll
        for (int j = 0; j < 4; ++j)
#pragma unroll
            for (int r = 0; r < 4; ++r) acc[i][j][r] = 0.f;

    float fc[4][2];
#pragma unroll
    for (int j = 0; j < 4; ++j) { fc[j][0] = 0.f; fc[j][1] = 0.f; }

    auto load_tile = [&](int t) {
        const int st = t & (S - 1);
        const int k0 = t * BK;
#pragma unroll
        for (int i = 0; i < 2; ++i) {   // A: 256 rows x 4 chunks of 16B
            int ch = tid + i * 512;
            int row = ch >> 2, c = ch & 3;
            cp16(sA + st * ASTG + row * AP + c * 8,
                 A + (size_t)row * NH2 + k0 + c * 8, true);
        }
#pragma unroll
        for (int i = 0; i < 3; ++i) {   // B: 32 rows x 36 chunks of 16B (1152 total)
            int ch = tid + i * 512;
            if (ch < BCH) {
                int r = ch / 36, c = ch % 36;
                int col = bn + c * 4;
                bool v = col < NISO;     // predicated-off cp.async zero-fills
                cp16(sB + st * BSTG + r * BNP + c * 4,
                     W + (size_t)(k0 + r) * NISO + (v ? col : 0), v);
            }
        }
        asm volatile("cp.async.commit_group;\n" ::: "memory");
    };

    load_tile(0); load_tile(1); load_tile(2);

    for (int t = 0; t < TK; ++t) {
        asm volatile("cp.async.wait_group 2;\n" ::: "memory");
        __syncthreads();

        if (t + 3 < TK) load_tile(t + 3);
        else asm volatile("cp.async.commit_group;\n" ::: "memory");

        const int st = t & (S - 1);
        const __half* a = sA + st * ASTG;
        const float*  b = sB + st * BSTG;

        // ---- tensor path: 128 cols ----
#pragma unroll
        for (int ks = 0; ks < 2; ++ks) {
            uint32_t af[4][4];
#pragma unroll
            for (int mt = 0; mt < 4; ++mt) {
                const uint32_t* ap0 = (const uint32_t*)(a + (wm + mt * 16 + g) * AP) + ks * 8;
                const uint32_t* ap1 = (const uint32_t*)(a + (wm + mt * 16 + g + 8) * AP) + ks * 8;
                af[mt][0] = ap0[tig];
                af[mt][1] = ap1[tig];
                af[mt][2] = ap0[tig + 4];
                af[mt][3] = ap1[tig + 4];
            }
            uint32_t bf[4][2];
#pragma unroll
            for (int nt = 0; nt < 4; ++nt) {
                const float* bp = b + (size_t)ks * 16 * BNP + wn + nt * 8 + g;
                float f0 = bp[(2 * tig) * BNP];
                float f1 = bp[(2 * tig + 1) * BNP];
                float f2 = bp[(2 * tig + 8) * BNP];
                float f3 = bp[(2 * tig + 9) * BNP];
                bf[nt][0] = pack_f16(f0, f1);
                bf[nt][1] = pack_f16(f2, f3);
            }
#pragma unroll
            for (int mt = 0; mt < 4; ++mt)
#pragma unroll
                for (int nt = 0; nt < 4; ++nt)
                    mma_f16(acc[mt][nt], af[mt], bf[nt]);
        }

        // ---- FFMA path: cols 128..143, full f32 ----
        {
            const uint32_t* aw = (const uint32_t*)a;   // A as packed half2 (k-pairs)
#pragma unroll 4
            for (int kk = 0; kk < 16; ++kk) {
                float2 b0 = *(const float2*)(b + (2 * kk) * BNP + 128 + 2 * cp);
                float2 b1 = *(const float2*)(b + (2 * kk + 1) * BNP + 128 + 2 * cp);
#pragma unroll
                for (int j = 0; j < 4; ++j) {
                    int row = rg + 64 * j;
                    uint32_t av = aw[row * 20 + kk];
                    float2 af2 = __half22float2(*(const __half2*)&av);
                    fc[j][0] += af2.x * b0.x + af2.y * b1.x;
                    fc[j][1] += af2.x * b0.y + af2.y * b1.y;
                }
            }
        }
    }

    __syncthreads();   // compute done; reuse smem

    // ---- epilogue: stage exp(logit+bias) for all 256 rows, 144 cols ----
    // tensor cols (two 128-row halves interleaved via warp's wm covering 0..255 already? no:
    // wm covers 0..255 directly (4 m-warps x 64). Stage all at once: sEp is 256 rows.
#pragma unroll
    for (int nt = 0; nt < 4; ++nt) {
        int cl0  = wn + nt * 8 + tig * 2;
        int col0 = bn + cl0;
        float bia0 = (col0 < NISO)     ? bias[col0]     : 0.f;
        float bia1 = (col0 + 1 < NISO) ? bias[col0 + 1] : 0.f;
#pragma unroll
        for (int mt = 0; mt < 4; ++mt) {
            int rl = wm + mt * 16 + g;
#pragma unroll
            for (int r = 0; r < 4; ++r) {
                int rr  = rl + ((r >= 2) ? 8 : 0);
                int cl  = cl0 + (r & 1);
                int col = col0 + (r & 1);
                if (col < NISO)
                    sEp[rr * BNP + cl] =
                        __expf(acc[mt][nt][r] + ((r & 1) ? bia1 : bia0));
            }
        }
    }
    // ffma cols
    {
        int col0 = bn + 128 + 2 * cp;
        float bia0 = (col0 < NISO)     ? bias[col0]     : 0.f;
        float bia1 = (col0 + 1 < NISO) ? bias[col0 + 1] : 0.f;
#pragma unroll
        for (int j = 0; j < 4; ++j) {
            int row = rg + 64 * j;
            if (col0 < NISO)     sEp[row * BNP + 128 + 2 * cp]     = __expf(fc[j][0] + bia0);
            if (col0 + 1 < NISO) sEp[row * BNP + 128 + 2 * cp + 1] = __expf(fc[j][1] + bia1);
        }
    }
    __syncthreads();

    // (a) denom red.v4 into denom2[gene][batch]
    {   // tensor cols: 128 cols x 256 rows; c = tid&127, rq = tid>>7 (0..3) -> 16 v4 each... 64 groups/col /4 = 16
        int c  = tid & 127;
        int rq = tid >> 7;               // 0..3
        int col = bn + c;
        if (col < NISO) {
            int gene = idx[col];
            float* dst = denom2 + (size_t)gene * NB;
#pragma unroll
            for (int p = 0; p < 16; ++p) {
                int r = (p * 4 + rq) * 4;    // 64 v4-groups, strided over rq
                float v0 = sEp[(r + 0) * BNP + c];
                float v1 = sEp[(r + 1) * BNP + c];
                float v2 = sEp[(r + 2) * BNP + c];
                float v3 = sEp[(r + 3) * BNP + c];
                asm volatile("red.global.add.v4.f32 [%0], {%1, %2, %3, %4};"
                             :: "l"(dst + r), "f"(v0), "f"(v1), "f"(v2), "f"(v3)
                             : "memory");
            }
        }
    }
    {   // ffma cols: 16 cols x 256 rows; c2 = tid&15, rq2 = tid>>4 (0..31) -> 2 v4 each
        int c2  = 128 + (tid & 15);
        int rq2 = tid >> 4;              // 0..31
        int col = bn + c2;
        if (col < NISO) {
            int gene = idx[col];
            float* dst = denom2 + (size_t)gene * NB;
#pragma unroll
            for (int p = 0; p < 2; ++p) {
                int r = (rq2 + 32 * p) * 4;
                float v0 = sEp[(r + 0) * BNP + c2];
                float v1 = sEp[(r + 1) * BNP + c2];
                float v2 = sEp[(r + 2) * BNP + c2];
                float v3 = sEp[(r + 3) * BNP + c2];
                asm volatile("red.global.add.v4.f32 [%0], {%1, %2, %3, %4};"
                             :: "l"(dst + r), "f"(v0), "f"(v1), "f"(v2), "f"(v3)
                             : "memory");
            }
        }
    }
    // (b) coalesced exp-logit stores: 256 rows x 36 float4
#pragma unroll
    for (int i = 0; i < 18; ++i) {
        int id = tid + i * 512;
        int rr = id / 36, c4 = id % 36;
        int col = bn + c4 * 4;
        if (col + 3 < NISO) {
            float4 v = *(const float4*)&sEp[rr * BNP + c4 * 4];
            *(float4*)&out[(size_t)rr * NISO + col] = v;
        } else {
#pragma unroll
            for (int e = 0; e < 4; ++e)
                if (col + e < NISO)
                    out[(size_t)rr * NISO + col + e] = sEp[rr * BNP + c4 * 4 + e];
        }
    }
}

// ================= Layers 1 & 2: fp16 GEMM =================
template<int BM, int BN, int WM, int WN>
__global__ void __launch_bounds__(256)
gemm_fp16_l12_kernel(const float* __restrict__ A, const float* __restrict__ W,
                     const float* __restrict__ bias, float* __restrict__ out,
                     int M, int N, int K)
{
    constexpr int S   = 3;
    constexpr int BK  = 16;
    constexpr int BKP = BK + 4;
    constexpr int BNP = BN + 4;
    constexpr int WARPS_N = BN / WN;
    constexpr int MT  = WM / 16;
    constexpr int NT  = WN / 8;
    constexpr int ACH = BM * BK / 4;
    constexpr int BCH = BK * BN / 4;

    extern __shared__ float smem12[];
    float* sAb = smem12;
    float* sBb = smem12 + S * BM * BKP;

    const int tid  = threadIdx.x;
    const int warp = tid >> 5;
    const int lane = tid & 31;
    const int gid  = lane >> 2;
    const int tig  = lane & 3;
    const int wm   = (warp / WARPS_N) * WM;
    const int wn   = (warp % WARPS_N) * WN;
    const int bm   = blockIdx.y * BM;
    const int bn   = blockIdx.x * BN;

    const int T = (K + BK - 1) / BK;

    float acc[MT][NT][4];
#pragma unroll
    for (int i = 0; i < MT; ++i)
#pragma unroll
        for (int j = 0; j < NT; ++j)
#pragma unroll
            for (int r = 0; r < 4; ++r) acc[i][j][r] = 0.f;

    auto load_tile = [&](int t, int stage) {
        const int k0 = t * BK;
        float* sa = sAb + stage * BM * BKP;
        float* sb = sBb + stage * BK * BNP;
#pragma unroll
        for (int i = 0; i < (ACH + 255) / 256; ++i) {
            int c = tid + i * 256;
            if (ACH % 256 == 0 || c < ACH) {
                int row = c / 4;
                int cc  = c & 3;
                int kk  = k0 + cc * 4;
                int kc  = kk < K ? kk : 0;
                cp16(sa + row * BKP + cc * 4, A + (size_t)(bm + row) * K + kc, kk < K);
            }
        }
#pragma unroll
        for (int i = 0; i < (BCH + 255) / 256; ++i) {
            int c = tid + i * 256;
            if (BCH % 256 == 0 || c < BCH) {
                int row = c / (BN / 4);
                int cc  = c % (BN / 4);
                int col = bn + cc * 4;
                int kk  = k0 + row;
                bool p  = (kk < K) && (col < N);
                int kc  = kk < K ? kk : 0;
                int cl  = col < N ? col : 0;
                cp16(sb + row * BNP + cc * 4, W + (size_t)kc * N + cl, p);
            }
        }
        asm volatile("cp.async.commit_group;\n" ::: "memory");
    };

    load_tile(0, 0);
    if (T > 1) load_tile(1, 1); else asm volatile("cp.async.commit_group;\n" ::: "memory");

    for (int t = 0; t < T; ++t) {
        asm volatile("cp.async.wait_group 1;\n" ::: "memory");
        __syncthreads();
        if (t + 2 < T) load_tile(t + 2, (t + 2) % S);
        else asm volatile("cp.async.commit_group;\n" ::: "memory");

        const float* a = sAb + (t % S) * BM * BKP;
        const float* b = sBb + (t % S) * BK * BNP;

        uint32_t ah[MT][4];
#pragma unroll
        for (int mt = 0; mt < MT; ++mt) {
            const float* ap0 = a + (size_t)(wm + mt * 16 + gid) * BKP;
            const float* ap1 = ap0 + 8 * BKP;
            float2 x0 = *(const float2*)(ap0 + 2 * tig);
            float2 x1 = *(const float2*)(ap1 + 2 * tig);
            float2 x2 = *(const float2*)(ap0 + 2 * tig + 8);
            float2 x3 = *(const float2*)(ap1 + 2 * tig + 8);
            ah[mt][0] = pack_f16(x0.x, x0.y);
            ah[mt][1] = pack_f16(x1.x, x1.y);
            ah[mt][2] = pack_f16(x2.x, x2.y);
            ah[mt][3] = pack_f16(x3.x, x3.y);
        }
        uint32_t bh[NT][2];
#pragma unroll
        for (int nt = 0; nt < NT; ++nt) {
            const float* bp = b + wn + nt * 8 + gid;
            float f0 = bp[(2 * tig) * BNP];
            float f1 = bp[(2 * tig + 1) * BNP];
            float f2 = bp[(2 * tig + 8) * BNP];
            float f3 = bp[(2 * tig + 9) * BNP];
            bh[nt][0] = pack_f16(f0, f1);
            bh[nt][1] = pack_f16(f2, f3);
        }
#pragma unroll
        for (int mt = 0; mt < MT; ++mt)
#pragma unroll
            for (int nt = 0; nt < NT; ++nt)
                mma_f16(acc[mt][nt], ah[mt], bh[nt]);
    }

#pragma unroll
    for (int nt = 0; nt < NT; ++nt) {
        int col0 = bn + wn + nt * 8 + tig * 2;
        float bia0 = (col0 < N)     ? bias[col0]     : 0.f;
        float bia1 = (col0 + 1 < N) ? bias[col0 + 1] : 0.f;
#pragma unroll
        for (int mt = 0; mt < MT; ++mt) {
            int row0 = bm + wm + mt * 16 + gid;
#pragma unroll
            for (int r = 0; r < 4; ++r) {
                int row = row0 + ((r >= 2) ? 8 : 0);
                int col = col0 + (r & 1);
                if (col < N)
                    out[(size_t)row * N + col] = acc[mt][nt][r] + ((r & 1) ? bia1 : bia0);
            }
        }
    }
}

// ---------------- LayerNorm + exact GELU (optionally also zero denom2) ----------------
template<typename OutT, bool ZERO>
__global__ void ln_gelu_kernel(const float* __restrict__ in, OutT* __restrict__ outp,
                               const float* __restrict__ g,
                               const float* __restrict__ beta, int H,
                               float* __restrict__ zbuf)
{
    int row = blockIdx.x;
    if (ZERO) {
        float4* z = (float4*)(zbuf + (size_t)row * NG);
        for (int i = threadIdx.x; i < NG / 4; i += blockDim.x)
            z[i] = make_float4(0.f, 0.f, 0.f, 0.f);
    }
    const float* x = in + (size_t)row * H;
    OutT* y = outp + (size_t)row * H;
    float s = 0.f, ss = 0.f;
    for (int i = threadIdx.x; i < H; i += blockDim.x) {
        float v = x[i];
        s += v; ss += v * v;
    }
    __shared__ float sh[2][8];
#pragma unroll
    for (int o = 16; o > 0; o >>= 1) {
        s  += __shfl_xor_sync(0xffffffffu, s, o);
        ss += __shfl_xor_sync(0xffffffffu, ss, o);
    }
    int w = threadIdx.x >> 5;
    if ((threadIdx.x & 31) == 0) { sh[0][w] = s; sh[1][w] = ss; }
    __syncthreads();
    float ts = 0.f, tss = 0.f;
#pragma unroll
    for (int i = 0; i < 8; ++i) { ts += sh[0][i]; tss += sh[1][i]; }
    float mu   = ts / (float)H;
    float var  = tss / (float)H - mu * mu;
    float rstd = rsqrtf(var + 1e-5f);
    for (int i = threadIdx.x; i < H; i += blockDim.x) {
        float v = (x[i] - mu) * rstd * g[i] + beta[i];
        float gl = 0.5f * v * (1.0f + erff(v * 0.70710678118654752f));
        if constexpr (sizeof(OutT) == 2) y[i] = __float2half_rn(gl);
        else                             y[i] = gl;
    }
}

// ---------------- denom transpose: [gene][batch] -> [batch][gene] ----------------
__global__ void transpose_kernel(const float* __restrict__ in, float* __restrict__ out)
{
    __shared__ float t[32][33];
    int g0 = blockIdx.x * 32, b0 = blockIdx.y * 32;
#pragma unroll
    for (int dy = 0; dy < 32; dy += 8) {
        int gg = g0 + threadIdx.y + dy;
        if (gg < NG) t[threadIdx.y + dy][threadIdx.x] = in[(size_t)gg * NB + b0 + threadIdx.x];
    }
    __syncthreads();
#pragma unroll
    for (int dy = 0; dy < 32; dy += 8) {
        int gg = g0 + threadIdx.x;
        int bb = b0 + threadIdx.y + dy;
        if (gg < NG) out[(size_t)bb * NG + gg] = t[threadIdx.x][threadIdx.y + dy];
    }
}

// ---------------- normalize: denom row resident in smem ----------------
__global__ void __launch_bounds__(512)
div_kernel(float* __restrict__ out, const float* __restrict__ denomT,
           const int* __restrict__ idx)
{
    extern __shared__ float sd[];      // NG floats = 100 KB
    int b = blockIdx.x;
    const float4* dr = (const float4*)(denomT + (size_t)b * NG);
    for (int i = threadIdx.x; i < NG / 4; i += blockDim.x)
        ((float4*)sd)[i] = dr[i];
    __syncthreads();
    float4* orow = (float4*)(out + (size_t)b * NISO);
    const int4* gi = (const int4*)idx;
    for (int i = threadIdx.x; i < NISO / 4; i += blockDim.x) {
        float4 v = orow[i];
        int4 g4 = gi[i];
        v.x /= fmaxf(sd[g4.x], 1e-8f);
        v.y /= fmaxf(sd[g4.y], 1e-8f);
        v.z /= fmaxf(sd[g4.z], 1e-8f);
        v.w /= fmaxf(sd[g4.w], 1e-8f);
        orow[i] = v;
    }
}

extern "C" void kernel_launch(void* const* d_in, const int* in_sizes, int n_in,
                              void* d_out, int out_size)
{
    const float* x   = (const float*)d_in[0];
    const int*   idx = (const int*)  d_in[1];
    const float* W1  = (const float*)d_in[2];
    const float* b1  = (const float*)d_in[3];
    const float* g1  = (const float*)d_in[4];
    const float* be1 = (const float*)d_in[5];
    const float* W2  = (const float*)d_in[6];
    const float* b2  = (const float*)d_in[7];
    const float* g2  = (const float*)d_in[8];
    const float* be2 = (const float*)d_in[9];
    const float* W3  = (const float*)d_in[10];
    const float* b3  = (const float*)d_in[11];
    float* out = (float*)d_out;

    float *h1, *h2, *denom2, *denomT;
    __half* h2h;
    cudaGetSymbolAddress((void**)&h1, g_h1);
    cudaGetSymbolAddress((void**)&h2, g_h2);
    cudaGetSymbolAddress((void**)&h2h, g_h2h);
    cudaGetSymbolAddress((void**)&denom2, g_denom2);
    cudaGetSymbolAddress((void**)&denomT, g_denomT);

    // ---- Layer 1: x @ W1 (fp16) ----
    {
        constexpr int BM = 64, BN = 64;
        constexpr int SM = 3 * (BM * 20 + 16 * (BN + 4)) * 4;
        auto k = gemm_fp16_l12_kernel<BM, BN, 32, 16>;
        cudaFuncSetAttribute(k, cudaFuncAttributeMaxDynamicSharedMemorySize, SM);
        dim3 grid(NH1 / BN, NB / BM);
        k<<<grid, 256, SM>>>(x, W1, b1, h1, NB, NH1, DIN);
    }
    ln_gelu_kernel<float, false><<<NB, 256>>>(h1, h1, g1, be1, NH1, nullptr);

    // ---- Layer 2: h1 @ W2 (fp16) ----
    {
        constexpr int BM = 32, BN = 64;
        constexpr int SM = 3 * (BM * 20 + 16 * (BN + 4)) * 4;
        auto k = gemm_fp16_l12_kernel<BM, BN, 16, 16>;
        cudaFuncSetAttribute(k, cudaFuncAttributeMaxDynamicSharedMemorySize, SM);
        dim3 grid(NH2 / BN, NB / BM);
        k<<<grid, 256, SM>>>(h1, W2, b2, h2, NB, NH2, NH1);
    }
    // LN2 also zeros denom2
    ln_gelu_kernel<__half, true><<<NB, 256>>>(h2, h2h, g2, be2, NH2, denom2);

    // ---- Layer 3: hybrid HMMA+FFMA GEMM, BM=256, BN=144, grid 695 ----
    {
        constexpr int SM3 = 4 * (256 * 40 * 2 + 32 * 148 * 4);  // 157696 B
        cudaFuncSetAttribute(gemm3_hyb_kernel, cudaFuncAttributeMaxDynamicSharedMemorySize, SM3);
        gemm3_hyb_kernel<<<(NISO + 143) / 144, 512, SM3>>>(h2h, W3, b3, idx, out, denom2);
    }

    // ---- transpose denom, then normalize with smem-resident denom rows ----
    {
        dim3 grid((NG + 31) / 32, NB / 32);
        transpose_kernel<<<grid, dim3(32, 8)>>>(denom2, denomT);

        constexpr int SMD = NG * 4;  // 100 KB
        cudaFuncSetAttribute(div_kernel, cudaFuncAttributeMaxDynamicSharedMemorySize, SMD);
        div_kernel<<<NB, 512, SMD>>>(out, denomT, idx);
    }
}

// round 13
// speedup vs baseline: 1.3297x; 1.3297x over previous
#include <cuda_runtime.h>
#include <cuda_fp16.h>
#include <math.h>
#include <stdint.h>

#define NB   256
#define DIN  5000
#define NH1  2048
#define NH2  1024
#define NISO 100000
#define NG   25000

// ---------------- scratch (static device arrays; allocation-free) ----------------
__device__ float  g_h1[NB * NH1];
__device__ float  g_h2[NB * NH2];
__device__ __half g_h2h[NB * NH2];
__device__ float  g_denom2[NG * NB];   // [gene][batch]
__device__ float  g_denomT[NB * NG];   // [batch][gene]

// ---------------- helpers ----------------
__device__ __forceinline__ void cp16(void* s, const void* g, bool pred) {
    uint32_t sa = (uint32_t)__cvta_generic_to_shared(s);
    int sz = pred ? 16 : 0;
    asm volatile("cp.async.cg.shared.global [%0], [%1], 16, %2;\n"
                 :: "r"(sa), "l"(g), "r"(sz) : "memory");
}

__device__ __forceinline__ void mma_f16(float* c, const uint32_t* a, const uint32_t* b) {
    asm volatile(
        "mma.sync.aligned.m16n8k16.row.col.f32.f16.f16.f32 "
        "{%0,%1,%2,%3}, {%4,%5,%6,%7}, {%8,%9}, {%0,%1,%2,%3};\n"
        : "+f"(c[0]), "+f"(c[1]), "+f"(c[2]), "+f"(c[3])
        : "r"(a[0]), "r"(a[1]), "r"(a[2]), "r"(a[3]), "r"(b[0]), "r"(b[1]));
}

// pack two f32 -> f16x2 register {lo=first, hi=second}
__device__ __forceinline__ uint32_t pack_f16(float lo, float hi) {
    uint32_t r;
    asm("cvt.rn.f16x2.f32 %0, %1, %2;" : "=r"(r) : "f"(hi), "f"(lo));
    return r;
}

// ================= GEMM3: fp16 mma.sync (f32 acc), BM=256, BN=128, BK=32 =================
// grid = ceil(NISO/128) = 782. A = g_h2h fp16; B = W3 fp32 converted in regs.
// Epilogue: bias + exp -> smem staging -> red.global.add.v4 denom + coalesced stores.
__global__ void __launch_bounds__(512, 1)
gemm3_fp16_kernel(const __half* __restrict__ A, const float* __restrict__ W,
                  const float* __restrict__ bias, const int* __restrict__ idx,
                  float* __restrict__ out, float* __restrict__ denom2)
{
    constexpr int S   = 4;
    constexpr int BK  = 32;
    constexpr int TK  = NH2 / BK;    // 32
    constexpr int AP  = 40;          // halfs per A row (32 + 8 pad) -> conflict-free
    constexpr int BNP = 132;         // floats per B row (128 + 4 pad)
    constexpr int ASTG = 256 * AP;   // halfs per A stage (20480 B)
    constexpr int BSTG = BK * BNP;   // floats per B stage (16896 B)

    extern __shared__ char sm3[];
    __half* sA  = (__half*)sm3;
    float*  sB  = (float*)(sm3 + S * ASTG * 2);
    float*  sEp = (float*)sm3;       // epilogue reuse: 128 x 132 floats

    const int tid  = threadIdx.x;
    const int warp = tid >> 5;
    const int lane = tid & 31;
    const int g    = lane >> 2;
    const int tig  = lane & 3;
    const int wm   = (warp >> 2) * 64;   // 0,64,128,192
    const int wn   = (warp & 3) * 32;    // 0,32,64,96
    const int bn   = blockIdx.x * 128;

    float acc[4][4][4];
#pragma unroll
    for (int i = 0; i < 4; ++i)
#pragma unroll
        for (int j = 0; j < 4; ++j)
#pragma unroll
            for (int r = 0; r < 4; ++r) acc[i][j][r] = 0.f;

    auto load_tile = [&](int t) {
        const int st = t & (S - 1);
        const int k0 = t * BK;
#pragma unroll
        for (int i = 0; i < 2; ++i) {   // A: 256 rows x 4 chunks of 16B
            int ch = tid + i * 512;
            int row = ch >> 2, c = ch & 3;
            cp16(sA + st * ASTG + row * AP + c * 8,
                 A + (size_t)row * NH2 + k0 + c * 8, true);
        }
#pragma unroll
        for (int i = 0; i < 2; ++i) {   // B: 32 rows x 32 chunks of 16B
            int ch = tid + i * 512;
            int r = ch >> 5, c = ch & 31;
            int col = bn + c * 4;
            bool v = col < NISO;
            cp16(sB + st * BSTG + r * BNP + c * 4,
                 W + (size_t)(k0 + r) * NISO + (v ? col : 0), v);
        }
        asm volatile("cp.async.commit_group;\n" ::: "memory");
    };

    load_tile(0); load_tile(1); load_tile(2);

    for (int t = 0; t < TK; ++t) {
        asm volatile("cp.async.wait_group 2;\n" ::: "memory");
        __syncthreads();

        if (t + 3 < TK) load_tile(t + 3);
        else asm volatile("cp.async.commit_group;\n" ::: "memory");

        const int st = t & (S - 1);
        const __half* a = sA + st * ASTG;
        const float*  b = sB + st * BSTG;

#pragma unroll
        for (int ks = 0; ks < 2; ++ks) {
            uint32_t af[4][4];
#pragma unroll
            for (int mt = 0; mt < 4; ++mt) {
                const uint32_t* ap0 = (const uint32_t*)(a + (wm + mt * 16 + g) * AP) + ks * 8;
                const uint32_t* ap1 = (const uint32_t*)(a + (wm + mt * 16 + g + 8) * AP) + ks * 8;
                af[mt][0] = ap0[tig];
                af[mt][1] = ap1[tig];
                af[mt][2] = ap0[tig + 4];
                af[mt][3] = ap1[tig + 4];
            }
            uint32_t bf[4][2];
#pragma unroll
            for (int nt = 0; nt < 4; ++nt) {
                const float* bp = b + (size_t)ks * 16 * BNP + wn + nt * 8 + g;
                float f0 = bp[(2 * tig) * BNP];
                float f1 = bp[(2 * tig + 1) * BNP];
                float f2 = bp[(2 * tig + 8) * BNP];
                float f3 = bp[(2 * tig + 9) * BNP];
                bf[nt][0] = pack_f16(f0, f1);
                bf[nt][1] = pack_f16(f2, f3);
            }
#pragma unroll
            for (int mt = 0; mt < 4; ++mt)
#pragma unroll
                for (int nt = 0; nt < 4; ++nt)
                    mma_f16(acc[mt][nt], af[mt], bf[nt]);
        }
    }

    __syncthreads();   // compute done; reuse smem

    // ---- epilogue: per 128-row half: stage exp, then v4-red denom + coalesced stores ----
    const int my_half = wm >> 7;
    for (int h = 0; h < 2; ++h) {
        if (my_half == h) {
            const int rl0 = wm & 127;
#pragma unroll
            for (int nt = 0; nt < 4; ++nt) {
                int cl0  = wn + nt * 8 + tig * 2;
                int col0 = bn + cl0;
                float bia0 = (col0 < NISO)     ? bias[col0]     : 0.f;
                float bia1 = (col0 + 1 < NISO) ? bias[col0 + 1] : 0.f;
#pragma unroll
                for (int mt = 0; mt < 4; ++mt) {
                    int rl = rl0 + mt * 16 + g;
#pragma unroll
                    for (int r = 0; r < 4; ++r) {
                        int rr  = rl + ((r >= 2) ? 8 : 0);
                        int cl  = cl0 + (r & 1);
                        int col = col0 + (r & 1);
                        if (col < NISO)
                            sEp[rr * BNP + cl] =
                                __expf(acc[mt][nt][r] + ((r & 1) ? bia1 : bia0));
                    }
                }
            }
        }
        __syncthreads();

        // (a) column pass: 4 consecutive batch rows per red.v4 into denom2[gene][batch]
        {
            int c  = tid & 127;
            int rq = tid >> 7;           // 0..3
            int col = bn + c;
            if (col < NISO) {
                int gene = idx[col];
                float* dst = denom2 + (size_t)gene * NB + h * 128;
#pragma unroll
                for (int p = 0; p < 8; ++p) {
                    int r = p * 16 + rq * 4;
                    float v0 = sEp[(r + 0) * BNP + c];
                    float v1 = sEp[(r + 1) * BNP + c];
                    float v2 = sEp[(r + 2) * BNP + c];
                    float v3 = sEp[(r + 3) * BNP + c];
                    asm volatile("red.global.add.v4.f32 [%0], {%1, %2, %3, %4};"
                                 :: "l"(dst + r), "f"(v0), "f"(v1), "f"(v2), "f"(v3)
                                 : "memory");
                }
            }
        }
        // (b) coalesced exp-logit stores: 128 rows x 32 float4
#pragma unroll
        for (int i = 0; i < 8; ++i) {
            int id = tid + i * 512;
            int rr = id >> 5, c4 = id & 31;
            int col = bn + c4 * 4;
            if (col < NISO) {
                float4 v = *(const float4*)&sEp[rr * BNP + c4 * 4];
                *(float4*)&out[(size_t)(h * 128 + rr) * NISO + col] = v;
            }
        }
        __syncthreads();
    }
}

// ================= Layers 1 & 2: fp16 GEMM =================
template<int BM, int BN, int WM, int WN>
__global__ void __launch_bounds__(256)
gemm_fp16_l12_kernel(const float* __restrict__ A, const float* __restrict__ W,
                     const float* __restrict__ bias, float* __restrict__ out,
                     int M, int N, int K)
{
    constexpr int S   = 3;
    constexpr int BK  = 16;
    constexpr int BKP = BK + 4;
    constexpr int BNP = BN + 4;
    constexpr int WARPS_N = BN / WN;
    constexpr int MT  = WM / 16;
    constexpr int NT  = WN / 8;
    constexpr int ACH = BM * BK / 4;
    constexpr int BCH = BK * BN / 4;

    extern __shared__ float smem12[];
    float* sAb = smem12;
    float* sBb = smem12 + S * BM * BKP;

    const int tid  = threadIdx.x;
    const int warp = tid >> 5;
    const int lane = tid & 31;
    const int gid  = lane >> 2;
    const int tig  = lane & 3;
    const int wm   = (warp / WARPS_N) * WM;
    const int wn   = (warp % WARPS_N) * WN;
    const int bm   = blockIdx.y * BM;
    const int bn   = blockIdx.x * BN;

    const int T = (K + BK - 1) / BK;

    float acc[MT][NT][4];
#pragma unroll
    for (int i = 0; i < MT; ++i)
#pragma unroll
        for (int j = 0; j < NT; ++j)
#pragma unroll
            for (int r = 0; r < 4; ++r) acc[i][j][r] = 0.f;

    auto load_tile = [&](int t, int stage) {
        const int k0 = t * BK;
        float* sa = sAb + stage * BM * BKP;
        float* sb = sBb + stage * BK * BNP;
#pragma unroll
        for (int i = 0; i < (ACH + 255) / 256; ++i) {
            int c = tid + i * 256;
            if (ACH % 256 == 0 || c < ACH) {
                int row = c / 4;
                int cc  = c & 3;
                int kk  = k0 + cc * 4;
                int kc  = kk < K ? kk : 0;
                cp16(sa + row * BKP + cc * 4, A + (size_t)(bm + row) * K + kc, kk < K);
            }
        }
#pragma unroll
        for (int i = 0; i < (BCH + 255) / 256; ++i) {
            int c = tid + i * 256;
            if (BCH % 256 == 0 || c < BCH) {
                int row = c / (BN / 4);
                int cc  = c % (BN / 4);
                int col = bn + cc * 4;
                int kk  = k0 + row;
                bool p  = (kk < K) && (col < N);
                int kc  = kk < K ? kk : 0;
                int cl  = col < N ? col : 0;
                cp16(sb + row * BNP + cc * 4, W + (size_t)kc * N + cl, p);
            }
        }
        asm volatile("cp.async.commit_group;\n" ::: "memory");
    };

    load_tile(0, 0);
    if (T > 1) load_tile(1, 1); else asm volatile("cp.async.commit_group;\n" ::: "memory");

    for (int t = 0; t < T; ++t) {
        asm volatile("cp.async.wait_group 1;\n" ::: "memory");
        __syncthreads();
        if (t + 2 < T) load_tile(t + 2, (t + 2) % S);
        else asm volatile("cp.async.commit_group;\n" ::: "memory");

        const float* a = sAb + (t % S) * BM * BKP;
        const float* b = sBb + (t % S) * BK * BNP;

        uint32_t ah[MT][4];
#pragma unroll
        for (int mt = 0; mt < MT; ++mt) {
            const float* ap0 = a + (size_t)(wm + mt * 16 + gid) * BKP;
            const float* ap1 = ap0 + 8 * BKP;
            float2 x0 = *(const float2*)(ap0 + 2 * tig);
            float2 x1 = *(const float2*)(ap1 + 2 * tig);
            float2 x2 = *(const float2*)(ap0 + 2 * tig + 8);
            float2 x3 = *(const float2*)(ap1 + 2 * tig + 8);
            ah[mt][0] = pack_f16(x0.x, x0.y);
            ah[mt][1] = pack_f16(x1.x, x1.y);
            ah[mt][2] = pack_f16(x2.x, x2.y);
            ah[mt][3] = pack_f16(x3.x, x3.y);
        }
        uint32_t bh[NT][2];
#pragma unroll
        for (int nt = 0; nt < NT; ++nt) {
            const float* bp = b + wn + nt * 8 + gid;
            float f0 = bp[(2 * tig) * BNP];
            float f1 = bp[(2 * tig + 1) * BNP];
            float f2 = bp[(2 * tig + 8) * BNP];
            float f3 = bp[(2 * tig + 9) * BNP];
            bh[nt][0] = pack_f16(f0, f1);
            bh[nt][1] = pack_f16(f2, f3);
        }
#pragma unroll
        for (int mt = 0; mt < MT; ++mt)
#pragma unroll
            for (int nt = 0; nt < NT; ++nt)
                mma_f16(acc[mt][nt], ah[mt], bh[nt]);
    }

#pragma unroll
    for (int nt = 0; nt < NT; ++nt) {
        int col0 = bn + wn + nt * 8 + tig * 2;
        float bia0 = (col0 < N)     ? bias[col0]     : 0.f;
        float bia1 = (col0 + 1 < N) ? bias[col0 + 1] : 0.f;
#pragma unroll
        for (int mt = 0; mt < MT; ++mt) {
            int row0 = bm + wm + mt * 16 + gid;
#pragma unroll
            for (int r = 0; r < 4; ++r) {
                int row = row0 + ((r >= 2) ? 8 : 0);
                int col = col0 + (r & 1);
                if (col < N)
                    out[(size_t)row * N + col] = acc[mt][nt][r] + ((r & 1) ? bia1 : bia0);
            }
        }
    }
}

// ---------------- LayerNorm + exact GELU (optionally also zero denom2) ----------------
template<typename OutT, bool ZERO>
__global__ void ln_gelu_kernel(const float* __restrict__ in, OutT* __restrict__ outp,
                               const float* __restrict__ g,
                               const float* __restrict__ beta, int H,
                               float* __restrict__ zbuf)
{
    int row = blockIdx.x;
    if (ZERO) {
        float4* z = (float4*)(zbuf + (size_t)row * NG);
        for (int i = threadIdx.x; i < NG / 4; i += blockDim.x)
            z[i] = make_float4(0.f, 0.f, 0.f, 0.f);
    }
    const float* x = in + (size_t)row * H;
    OutT* y = outp + (size_t)row * H;
    float s = 0.f, ss = 0.f;
    for (int i = threadIdx.x; i < H; i += blockDim.x) {
        float v = x[i];
        s += v; ss += v * v;
    }
    __shared__ float sh[2][8];
#pragma unroll
    for (int o = 16; o > 0; o >>= 1) {
        s  += __shfl_xor_sync(0xffffffffu, s, o);
        ss += __shfl_xor_sync(0xffffffffu, ss, o);
    }
    int w = threadIdx.x >> 5;
    if ((threadIdx.x & 31) == 0) { sh[0][w] = s; sh[1][w] = ss; }
    __syncthreads();
    float ts = 0.f, tss = 0.f;
#pragma unroll
    for (int i = 0; i < 8; ++i) { ts += sh[0][i]; tss += sh[1][i]; }
    float mu   = ts / (float)H;
    float var  = tss / (float)H - mu * mu;
    float rstd = rsqrtf(var + 1e-5f);
    for (int i = threadIdx.x; i < H; i += blockDim.x) {
        float v = (x[i] - mu) * rstd * g[i] + beta[i];
        float gl = 0.5f * v * (1.0f + erff(v * 0.70710678118654752f));
        if constexpr (sizeof(OutT) == 2) y[i] = __float2half_rn(gl);
        else                             y[i] = gl;
    }
}

// ---------------- denom transpose: [gene][batch] -> [batch][gene] ----------------
__global__ void transpose_kernel(const float* __restrict__ in, float* __restrict__ out)
{
    __shared__ float t[32][33];
    int g0 = blockIdx.x * 32, b0 = blockIdx.y * 32;
#pragma unroll
    for (int dy = 0; dy < 32; dy += 8) {
        int gg = g0 + threadIdx.y + dy;
        if (gg < NG) t[threadIdx.y + dy][threadIdx.x] = in[(size_t)gg * NB + b0 + threadIdx.x];
    }
    __syncthreads();
#pragma unroll
    for (int dy = 0; dy < 32; dy += 8) {
        int gg = g0 + threadIdx.x;
        int bb = b0 + threadIdx.y + dy;
        if (gg < NG) out[(size_t)bb * NG + gg] = t[threadIdx.x][threadIdx.y + dy];
    }
}

// ---------------- normalize: reciprocal denom row resident in smem ----------------
__global__ void __launch_bounds__(512)
div_kernel(float* __restrict__ out, const float* __restrict__ denomT,
           const int* __restrict__ idx)
{
    extern __shared__ float sd[];      // NG floats = 100 KB (reciprocals)
    int b = blockIdx.x;
    const float4* dr = (const float4*)(denomT + (size_t)b * NG);
    for (int i = threadIdx.x; i < NG / 4; i += blockDim.x) {
        float4 d = dr[i];
        float4 rc;
        rc.x = 1.0f / fmaxf(d.x, 1e-8f);
        rc.y = 1.0f / fmaxf(d.y, 1e-8f);
        rc.z = 1.0f / fmaxf(d.z, 1e-8f);
        rc.w = 1.0f / fmaxf(d.w, 1e-8f);
        ((float4*)sd)[i] = rc;
    }
    __syncthreads();
    float4* orow = (float4*)(out + (size_t)b * NISO);
    const int4* gi = (const int4*)idx;
    for (int i = threadIdx.x; i < NISO / 4; i += blockDim.x) {
        float4 v = orow[i];
        int4 g4 = gi[i];
        v.x *= sd[g4.x];
        v.y *= sd[g4.y];
        v.z *= sd[g4.z];
        v.w *= sd[g4.w];
        orow[i] = v;
    }
}

extern "C" void kernel_launch(void* const* d_in, const int* in_sizes, int n_in,
                              void* d_out, int out_size)
{
    const float* x   = (const float*)d_in[0];
    const int*   idx = (const int*)  d_in[1];
    const float* W1  = (const float*)d_in[2];
    const float* b1  = (const float*)d_in[3];
    const float* g1  = (const float*)d_in[4];
    const float* be1 = (const float*)d_in[5];
    const float* W2  = (const float*)d_in[6];
    const float* b2  = (const float*)d_in[7];
    const float* g2  = (const float*)d_in[8];
    const float* be2 = (const float*)d_in[9];
    const float* W3  = (const float*)d_in[10];
    const float* b3  = (const float*)d_in[11];
    float* out = (float*)d_out;

    float *h1, *h2, *denom2, *denomT;
    __half* h2h;
    cudaGetSymbolAddress((void**)&h1, g_h1);
    cudaGetSymbolAddress((void**)&h2, g_h2);
    cudaGetSymbolAddress((void**)&h2h, g_h2h);
    cudaGetSymbolAddress((void**)&denom2, g_denom2);
    cudaGetSymbolAddress((void**)&denomT, g_denomT);

    // ---- Layer 1: x @ W1 (fp16) ----
    {
        constexpr int BM = 64, BN = 64;
        constexpr int SM = 3 * (BM * 20 + 16 * (BN + 4)) * 4;
        auto k = gemm_fp16_l12_kernel<BM, BN, 32, 16>;
        cudaFuncSetAttribute(k, cudaFuncAttributeMaxDynamicSharedMemorySize, SM);
        dim3 grid(NH1 / BN, NB / BM);
        k<<<grid, 256, SM>>>(x, W1, b1, h1, NB, NH1, DIN);
    }
    ln_gelu_kernel<float, false><<<NB, 256>>>(h1, h1, g1, be1, NH1, nullptr);

    // ---- Layer 2: h1 @ W2 (fp16) ----
    {
        constexpr int BM = 32, BN = 64;
        constexpr int SM = 3 * (BM * 20 + 16 * (BN + 4)) * 4;
        auto k = gemm_fp16_l12_kernel<BM, BN, 16, 16>;
        cudaFuncSetAttribute(k, cudaFuncAttributeMaxDynamicSharedMemorySize, SM);
        dim3 grid(NH2 / BN, NB / BM);
        k<<<grid, 256, SM>>>(h1, W2, b2, h2, NB, NH2, NH1);
    }
    // LN2 also zeros denom2
    ln_gelu_kernel<__half, true><<<NB, 256>>>(h2, h2h, g2, be2, NH2, denom2);

    // ---- Layer 3: fp16 mma GEMM, BM=256 x BN=128, BK=32 (best-known config) ----
    {
        constexpr int ASTG = 256 * 40;            // halfs
        constexpr int BSTG = 32 * 132;            // floats
        constexpr int SM3  = 4 * (ASTG * 2 + BSTG * 4);  // 149504 B
        cudaFuncSetAttribute(gemm3_fp16_kernel, cudaFuncAttributeMaxDynamicSharedMemorySize, SM3);
        gemm3_fp16_kernel<<<(NISO + 127) / 128, 512, SM3>>>(h2h, W3, b3, idx, out, denom2);
    }

    // ---- transpose denom, then normalize with smem-resident reciprocal rows ----
    {
        dim3 grid((NG + 31) / 32, NB / 32);
        transpose_kernel<<<grid, dim3(32, 8)>>>(denom2, denomT);

        constexpr int SMD = NG * 4;  // 100 KB
        cudaFuncSetAttribute(div_kernel, cudaFuncAttributeMaxDynamicSharedMemorySize, SMD);
        div_kernel<<<NB, 512, SMD>>>(out, denomT, idx);
    }
}

// round 14
// speedup vs baseline: 1.4005x; 1.0532x over previous
#include <cuda_runtime.h>
#include <cuda_fp16.h>
#include <math.h>
#include <stdint.h>

#define NB   256
#define DIN  5000
#define NH1  2048
#define NH2  1024
#define NISO 100000
#define NG   25000

// ---------------- scratch (static device arrays; allocation-free) ----------------
__device__ float  g_h1[NB * NH1];
__device__ float  g_h2[NB * NH2];
__device__ __half g_h2h[NB * NH2];
__device__ float  g_denom2[NG * NB];   // [gene][batch]
__device__ float  g_denomT[NB * NG];   // [batch][gene]
__device__ __half g_exph[(size_t)NB * NISO];  // fp16 exp-logit staging (51.2 MB)

// ---------------- helpers ----------------
__device__ __forceinline__ void cp16(void* s, const void* g, bool pred) {
    uint32_t sa = (uint32_t)__cvta_generic_to_shared(s);
    int sz = pred ? 16 : 0;
    asm volatile("cp.async.cg.shared.global [%0], [%1], 16, %2;\n"
                 :: "r"(sa), "l"(g), "r"(sz) : "memory");
}

__device__ __forceinline__ void mma_f16(float* c, const uint32_t* a, const uint32_t* b) {
    asm volatile(
        "mma.sync.aligned.m16n8k16.row.col.f32.f16.f16.f32 "
        "{%0,%1,%2,%3}, {%4,%5,%6,%7}, {%8,%9}, {%0,%1,%2,%3};\n"
        : "+f"(c[0]), "+f"(c[1]), "+f"(c[2]), "+f"(c[3])
        : "r"(a[0]), "r"(a[1]), "r"(a[2]), "r"(a[3]), "r"(b[0]), "r"(b[1]));
}

// pack two f32 -> f16x2 register {lo=first, hi=second}
__device__ __forceinline__ uint32_t pack_f16(float lo, float hi) {
    uint32_t r;
    asm("cvt.rn.f16x2.f32 %0, %1, %2;" : "=r"(r) : "f"(hi), "f"(lo));
    return r;
}

// ================= GEMM3: fp16 mma.sync (f32 acc), BM=256, BN=128, BK=32 =================
// grid = ceil(NISO/128) = 782. A = g_h2h fp16; B = W3 fp32 converted in regs.
// Epilogue: bias + exp -> smem staging -> red.global.add.v4 denom + fp16 numerator stores.
__global__ void __launch_bounds__(512, 1)
gemm3_fp16_kernel(const __half* __restrict__ A, const float* __restrict__ W,
                  const float* __restrict__ bias, const int* __restrict__ idx,
                  __half* __restrict__ expH, float* __restrict__ denom2)
{
    constexpr int S   = 4;
    constexpr int BK  = 32;
    constexpr int TK  = NH2 / BK;    // 32
    constexpr int AP  = 40;          // halfs per A row (32 + 8 pad) -> conflict-free
    constexpr int BNP = 132;         // floats per B row (128 + 4 pad)
    constexpr int ASTG = 256 * AP;   // halfs per A stage (20480 B)
    constexpr int BSTG = BK * BNP;   // floats per B stage (16896 B)

    extern __shared__ char sm3[];
    __half* sA  = (__half*)sm3;
    float*  sB  = (float*)(sm3 + S * ASTG * 2);
    float*  sEp = (float*)sm3;       // epilogue reuse: 128 x 132 floats

    const int tid  = threadIdx.x;
    const int warp = tid >> 5;
    const int lane = tid & 31;
    const int g    = lane >> 2;
    const int tig  = lane & 3;
    const int wm   = (warp >> 2) * 64;   // 0,64,128,192
    const int wn   = (warp & 3) * 32;    // 0,32,64,96
    const int bn   = blockIdx.x * 128;

    float acc[4][4][4];
#pragma unroll
    for (int i = 0; i < 4; ++i)
#pragma unroll
        for (int j = 0; j < 4; ++j)
#pragma unroll
            for (int r = 0; r < 4; ++r) acc[i][j][r] = 0.f;

    auto load_tile = [&](int t) {
        const int st = t & (S - 1);
        const int k0 = t * BK;
#pragma unroll
        for (int i = 0; i < 2; ++i) {   // A: 256 rows x 4 chunks of 16B
            int ch = tid + i * 512;
            int row = ch >> 2, c = ch & 3;
            cp16(sA + st * ASTG + row * AP + c * 8,
                 A + (size_t)row * NH2 + k0 + c * 8, true);
        }
#pragma unroll
        for (int i = 0; i < 2; ++i) {   // B: 32 rows x 32 chunks of 16B
            int ch = tid + i * 512;
            int r = ch >> 5, c = ch & 31;
            int col = bn + c * 4;
            bool v = col < NISO;
            cp16(sB + st * BSTG + r * BNP + c * 4,
                 W + (size_t)(k0 + r) * NISO + (v ? col : 0), v);
        }
        asm volatile("cp.async.commit_group;\n" ::: "memory");
    };

    load_tile(0); load_tile(1); load_tile(2);

    for (int t = 0; t < TK; ++t) {
        asm volatile("cp.async.wait_group 2;\n" ::: "memory");
        __syncthreads();

        if (t + 3 < TK) load_tile(t + 3);
        else asm volatile("cp.async.commit_group;\n" ::: "memory");

        const int st = t & (S - 1);
        const __half* a = sA + st * ASTG;
        const float*  b = sB + st * BSTG;

#pragma unroll
        for (int ks = 0; ks < 2; ++ks) {
            uint32_t af[4][4];
#pragma unroll
            for (int mt = 0; mt < 4; ++mt) {
                const uint32_t* ap0 = (const uint32_t*)(a + (wm + mt * 16 + g) * AP) + ks * 8;
                const uint32_t* ap1 = (const uint32_t*)(a + (wm + mt * 16 + g + 8) * AP) + ks * 8;
                af[mt][0] = ap0[tig];
                af[mt][1] = ap1[tig];
                af[mt][2] = ap0[tig + 4];
                af[mt][3] = ap1[tig + 4];
            }
            uint32_t bf[4][2];
#pragma unroll
            for (int nt = 0; nt < 4; ++nt) {
                const float* bp = b + (size_t)ks * 16 * BNP + wn + nt * 8 + g;
                float f0 = bp[(2 * tig) * BNP];
                float f1 = bp[(2 * tig + 1) * BNP];
                float f2 = bp[(2 * tig + 8) * BNP];
                float f3 = bp[(2 * tig + 9) * BNP];
                bf[nt][0] = pack_f16(f0, f1);
                bf[nt][1] = pack_f16(f2, f3);
            }
#pragma unroll
            for (int mt = 0; mt < 4; ++mt)
#pragma unroll
                for (int nt = 0; nt < 4; ++nt)
                    mma_f16(acc[mt][nt], af[mt], bf[nt]);
        }
    }

    __syncthreads();   // compute done; reuse smem

    // ---- epilogue: per 128-row half: stage exp, then v4-red denom + fp16 stores ----
    const int my_half = wm >> 7;
    for (int h = 0; h < 2; ++h) {
        if (my_half == h) {
            const int rl0 = wm & 127;
#pragma unroll
            for (int nt = 0; nt < 4; ++nt) {
                int cl0  = wn + nt * 8 + tig * 2;
                int col0 = bn + cl0;
                float bia0 = (col0 < NISO)     ? bias[col0]     : 0.f;
                float bia1 = (col0 + 1 < NISO) ? bias[col0 + 1] : 0.f;
#pragma unroll
                for (int mt = 0; mt < 4; ++mt) {
                    int rl = rl0 + mt * 16 + g;
#pragma unroll
                    for (int r = 0; r < 4; ++r) {
                        int rr  = rl + ((r >= 2) ? 8 : 0);
                        int cl  = cl0 + (r & 1);
                        int col = col0 + (r & 1);
                        if (col < NISO)
                            sEp[rr * BNP + cl] =
                                __expf(acc[mt][nt][r] + ((r & 1) ? bia1 : bia0));
                    }
                }
            }
        }
        __syncthreads();

        // (a) column pass: 4 consecutive batch rows per red.v4 into denom2[gene][batch]
        {
            int c  = tid & 127;
            int rq = tid >> 7;           // 0..3
            int col = bn + c;
            if (col < NISO) {
                int gene = idx[col];
                float* dst = denom2 + (size_t)gene * NB + h * 128;
#pragma unroll
                for (int p = 0; p < 8; ++p) {
                    int r = p * 16 + rq * 4;
                    float v0 = sEp[(r + 0) * BNP + c];
                    float v1 = sEp[(r + 1) * BNP + c];
                    float v2 = sEp[(r + 2) * BNP + c];
                    float v3 = sEp[(r + 3) * BNP + c];
                    asm volatile("red.global.add.v4.f32 [%0], {%1, %2, %3, %4};"
                                 :: "l"(dst + r), "f"(v0), "f"(v1), "f"(v2), "f"(v3)
                                 : "memory");
                }
            }
        }
        // (b) coalesced fp16 numerator stores: 128 rows x 32 groups of 4 cols (8B)
#pragma unroll
        for (int i = 0; i < 8; ++i) {
            int id = tid + i * 512;
            int rr = id >> 5, c4 = id & 31;
            int col = bn + c4 * 4;
            if (col < NISO) {
                float4 v = *(const float4*)&sEp[rr * BNP + c4 * 4];
                uint2 u;
                u.x = pack_f16(v.x, v.y);
                u.y = pack_f16(v.z, v.w);
                *(uint2*)&expH[(size_t)(h * 128 + rr) * NISO + col] = u;
            }
        }
        __syncthreads();
    }
}

// ================= Layers 1 & 2: fp16 GEMM =================
template<int BM, int BN, int WM, int WN>
__global__ void __launch_bounds__(256)
gemm_fp16_l12_kernel(const float* __restrict__ A, const float* __restrict__ W,
                     const float* __restrict__ bias, float* __restrict__ out,
                     int M, int N, int K)
{
    constexpr int S   = 3;
    constexpr int BK  = 16;
    constexpr int BKP = BK + 4;
    constexpr int BNP = BN + 4;
    constexpr int WARPS_N = BN / WN;
    constexpr int MT  = WM / 16;
    constexpr int NT  = WN / 8;
    constexpr int ACH = BM * BK / 4;
    constexpr int BCH = BK * BN / 4;

    extern __shared__ float smem12[];
    float* sAb = smem12;
    float* sBb = smem12 + S * BM * BKP;

    const int tid  = threadIdx.x;
    const int warp = tid >> 5;
    const int lane = tid & 31;
    const int gid  = lane >> 2;
    const int tig  = lane & 3;
    const int wm   = (warp / WARPS_N) * WM;
    const int wn   = (warp % WARPS_N) * WN;
    const int bm   = blockIdx.y * BM;
    const int bn   = blockIdx.x * BN;

    const int T = (K + BK - 1) / BK;

    float acc[MT][NT][4];
#pragma unroll
    for (int i = 0; i < MT; ++i)
#pragma unroll
        for (int j = 0; j < NT; ++j)
#pragma unroll
            for (int r = 0; r < 4; ++r) acc[i][j][r] = 0.f;

    auto load_tile = [&](int t, int stage) {
        const int k0 = t * BK;
        float* sa = sAb + stage * BM * BKP;
        float* sb = sBb + stage * BK * BNP;
#pragma unroll
        for (int i = 0; i < (ACH + 255) / 256; ++i) {
            int c = tid + i * 256;
            if (ACH % 256 == 0 || c < ACH) {
                int row = c / 4;
                int cc  = c & 3;
                int kk  = k0 + cc * 4;
                int kc  = kk < K ? kk : 0;
                cp16(sa + row * BKP + cc * 4, A + (size_t)(bm + row) * K + kc, kk < K);
            }
        }
#pragma unroll
        for (int i = 0; i < (BCH + 255) / 256; ++i) {
            int c = tid + i * 256;
            if (BCH % 256 == 0 || c < BCH) {
                int row = c / (BN / 4);
                int cc  = c % (BN / 4);
                int col = bn + cc * 4;
                int kk  = k0 + row;
                bool p  = (kk < K) && (col < N);
                int kc  = kk < K ? kk : 0;
                int cl  = col < N ? col : 0;
                cp16(sb + row * BNP + cc * 4, W + (size_t)kc * N + cl, p);
            }
        }
        asm volatile("cp.async.commit_group;\n" ::: "memory");
    };

    load_tile(0, 0);
    if (T > 1) load_tile(1, 1); else asm volatile("cp.async.commit_group;\n" ::: "memory");

    for (int t = 0; t < T; ++t) {
        asm volatile("cp.async.wait_group 1;\n" ::: "memory");
        __syncthreads();
        if (t + 2 < T) load_tile(t + 2, (t + 2) % S);
        else asm volatile("cp.async.commit_group;\n" ::: "memory");

        const float* a = sAb + (t % S) * BM * BKP;
        const float* b = sBb + (t % S) * BK * BNP;

        uint32_t ah[MT][4];
#pragma unroll
        for (int mt = 0; mt < MT; ++mt) {
            const float* ap0 = a + (size_t)(wm + mt * 16 + gid) * BKP;
            const float* ap1 = ap0 + 8 * BKP;
            float2 x0 = *(const float2*)(ap0 + 2 * tig);
            float2 x1 = *(const float2*)(ap1 + 2 * tig);
            float2 x2 = *(const float2*)(ap0 + 2 * tig + 8);
            float2 x3 = *(const float2*)(ap1 + 2 * tig + 8);
            ah[mt][0] = pack_f16(x0.x, x0.y);
            ah[mt][1] = pack_f16(x1.x, x1.y);
            ah[mt][2] = pack_f16(x2.x, x2.y);
            ah[mt][3] = pack_f16(x3.x, x3.y);
        }
        uint32_t bh[NT][2];
#pragma unroll
        for (int nt = 0; nt < NT; ++nt) {
            const float* bp = b + wn + nt * 8 + gid;
            float f0 = bp[(2 * tig) * BNP];
            float f1 = bp[(2 * tig + 1) * BNP];
            float f2 = bp[(2 * tig + 8) * BNP];
            float f3 = bp[(2 * tig + 9) * BNP];
            bh[nt][0] = pack_f16(f0, f1);
            bh[nt][1] = pack_f16(f2, f3);
        }
#pragma unroll
        for (int mt = 0; mt < MT; ++mt)
#pragma unroll
            for (int nt = 0; nt < NT; ++nt)
                mma_f16(acc[mt][nt], ah[mt], bh[nt]);
    }

#pragma unroll
    for (int nt = 0; nt < NT; ++nt) {
        int col0 = bn + wn + nt * 8 + tig * 2;
        float bia0 = (col0 < N)     ? bias[col0]     : 0.f;
        float bia1 = (col0 + 1 < N) ? bias[col0 + 1] : 0.f;
#pragma unroll
        for (int mt = 0; mt < MT; ++mt) {
            int row0 = bm + wm + mt * 16 + gid;
#pragma unroll
            for (int r = 0; r < 4; ++r) {
                int row = row0 + ((r >= 2) ? 8 : 0);
                int col = col0 + (r & 1);
                if (col < N)
                    out[(size_t)row * N + col] = acc[mt][nt][r] + ((r & 1) ? bia1 : bia0);
            }
        }
    }
}

// ---------------- LayerNorm + exact GELU (optionally also zero denom2) ----------------
template<typename OutT, bool ZERO>
__global__ void ln_gelu_kernel(const float* __restrict__ in, OutT* __restrict__ outp,
                               const float* __restrict__ g,
                               const float* __restrict__ beta, int H,
                               float* __restrict__ zbuf)
{
    int row = blockIdx.x;
    if (ZERO) {
        float4* z = (float4*)(zbuf + (size_t)row * NG);
        for (int i = threadIdx.x; i < NG / 4; i += blockDim.x)
            z[i] = make_float4(0.f, 0.f, 0.f, 0.f);
    }
    const float* x = in + (size_t)row * H;
    OutT* y = outp + (size_t)row * H;
    float s = 0.f, ss = 0.f;
    for (int i = threadIdx.x; i < H; i += blockDim.x) {
        float v = x[i];
        s += v; ss += v * v;
    }
    __shared__ float sh[2][8];
#pragma unroll
    for (int o = 16; o > 0; o >>= 1) {
        s  += __shfl_xor_sync(0xffffffffu, s, o);
        ss += __shfl_xor_sync(0xffffffffu, ss, o);
    }
    int w = threadIdx.x >> 5;
    if ((threadIdx.x & 31) == 0) { sh[0][w] = s; sh[1][w] = ss; }
    __syncthreads();
    float ts = 0.f, tss = 0.f;
#pragma unroll
    for (int i = 0; i < 8; ++i) { ts += sh[0][i]; tss += sh[1][i]; }
    float mu   = ts / (float)H;
    float var  = tss / (float)H - mu * mu;
    float rstd = rsqrtf(var + 1e-5f);
    for (int i = threadIdx.x; i < H; i += blockDim.x) {
        float v = (x[i] - mu) * rstd * g[i] + beta[i];
        float gl = 0.5f * v * (1.0f + erff(v * 0.70710678118654752f));
        if constexpr (sizeof(OutT) == 2) y[i] = __float2half_rn(gl);
        else                             y[i] = gl;
    }
}

// ---------------- denom transpose: [gene][batch] -> [batch][gene] ----------------
__global__ void transpose_kernel(const float* __restrict__ in, float* __restrict__ out)
{
    __shared__ float t[32][33];
    int g0 = blockIdx.x * 32, b0 = blockIdx.y * 32;
#pragma unroll
    for (int dy = 0; dy < 32; dy += 8) {
        int gg = g0 + threadIdx.y + dy;
        if (gg < NG) t[threadIdx.y + dy][threadIdx.x] = in[(size_t)gg * NB + b0 + threadIdx.x];
    }
    __syncthreads();
#pragma unroll
    for (int dy = 0; dy < 32; dy += 8) {
        int gg = g0 + threadIdx.x;
        int bb = b0 + threadIdx.y + dy;
        if (gg < NG) out[(size_t)bb * NG + gg] = t[threadIdx.x][threadIdx.y + dy];
    }
}

// ---------------- normalize: fp16 numerator * smem-resident reciprocal ----------------
__global__ void __launch_bounds__(512)
div_kernel(float* __restrict__ out, const __half* __restrict__ expH,
           const float* __restrict__ denomT, const int* __restrict__ idx)
{
    extern __shared__ float sd[];      // NG floats = 100 KB (reciprocals)
    int b = blockIdx.x;
    const float4* dr = (const float4*)(denomT + (size_t)b * NG);
    for (int i = threadIdx.x; i < NG / 4; i += blockDim.x) {
        float4 d = dr[i];
        float4 rc;
        rc.x = 1.0f / fmaxf(d.x, 1e-8f);
        rc.y = 1.0f / fmaxf(d.y, 1e-8f);
        rc.z = 1.0f / fmaxf(d.z, 1e-8f);
        rc.w = 1.0f / fmaxf(d.w, 1e-8f);
        ((float4*)sd)[i] = rc;
    }
    __syncthreads();
    float4* orow = (float4*)(out + (size_t)b * NISO);
    const uint2* erow = (const uint2*)(expH + (size_t)b * NISO);
    const int4* gi = (const int4*)idx;
    for (int i = threadIdx.x; i < NISO / 4; i += blockDim.x) {
        uint2 u = erow[i];
        float2 e01 = __half22float2(*(const __half2*)&u.x);
        float2 e23 = __half22float2(*(const __half2*)&u.y);
        int4 g4 = gi[i];
        float4 v;
        v.x = e01.x * sd[g4.x];
        v.y = e01.y * sd[g4.y];
        v.z = e23.x * sd[g4.z];
        v.w = e23.y * sd[g4.w];
        orow[i] = v;
    }
}

extern "C" void kernel_launch(void* const* d_in, const int* in_sizes, int n_in,
                              void* d_out, int out_size)
{
    const float* x   = (const float*)d_in[0];
    const int*   idx = (const int*)  d_in[1];
    const float* W1  = (const float*)d_in[2];
    const float* b1  = (const float*)d_in[3];
    const float* g1  = (const float*)d_in[4];
    const float* be1 = (const float*)d_in[5];
    const float* W2  = (const float*)d_in[6];
    const float* b2  = (const float*)d_in[7];
    const float* g2  = (const float*)d_in[8];
    const float* be2 = (const float*)d_in[9];
    const float* W3  = (const float*)d_in[10];
    const float* b3  = (const float*)d_in[11];
    float* out = (float*)d_out;

    float *h1, *h2, *denom2, *denomT;
    __half *h2h, *exph;
    cudaGetSymbolAddress((void**)&h1, g_h1);
    cudaGetSymbolAddress((void**)&h2, g_h2);
    cudaGetSymbolAddress((void**)&h2h, g_h2h);
    cudaGetSymbolAddress((void**)&denom2, g_denom2);
    cudaGetSymbolAddress((void**)&denomT, g_denomT);
    cudaGetSymbolAddress((void**)&exph, g_exph);

    // ---- Layer 1: x @ W1 (fp16), 256 CTAs for full-chip fill ----
    {
        constexpr int BM = 32, BN = 64;
        constexpr int SM = 3 * (BM * 20 + 16 * (BN + 4)) * 4;
        auto k = gemm_fp16_l12_kernel<BM, BN, 16, 16>;
        cudaFuncSetAttribute(k, cudaFuncAttributeMaxDynamicSharedMemorySize, SM);
        dim3 grid(NH1 / BN, NB / BM);
        k<<<grid, 256, SM>>>(x, W1, b1, h1, NB, NH1, DIN);
    }
    ln_gelu_kernel<float, false><<<NB, 256>>>(h1, h1, g1, be1, NH1, nullptr);

    // ---- Layer 2: h1 @ W2 (fp16) ----
    {
        constexpr int BM = 32, BN = 64;
        constexpr int SM = 3 * (BM * 20 + 16 * (BN + 4)) * 4;
        auto k = gemm_fp16_l12_kernel<BM, BN, 16, 16>;
        cudaFuncSetAttribute(k, cudaFuncAttributeMaxDynamicSharedMemorySize, SM);
        dim3 grid(NH2 / BN, NB / BM);
        k<<<grid, 256, SM>>>(h1, W2, b2, h2, NB, NH2, NH1);
    }
    // LN2 also zeros denom2
    ln_gelu_kernel<__half, true><<<NB, 256>>>(h2, h2h, g2, be2, NH2, denom2);

    // ---- Layer 3: fp16 mma GEMM, BM=256 x BN=128, BK=32 ----
    {
        constexpr int ASTG = 256 * 40;            // halfs
        constexpr int BSTG = 32 * 132;            // floats
        constexpr int SM3  = 4 * (ASTG * 2 + BSTG * 4);  // 149504 B
        cudaFuncSetAttribute(gemm3_fp16_kernel, cudaFuncAttributeMaxDynamicSharedMemorySize, SM3);
        gemm3_fp16_kernel<<<(NISO + 127) / 128, 512, SM3>>>(h2h, W3, b3, idx, exph, denom2);
    }

    // ---- transpose denom, then normalize fp16 numerators with reciprocal rows ----
    {
        dim3 grid((NG + 31) / 32, NB / 32);
        transpose_kernel<<<grid, dim3(32, 8)>>>(denom2, denomT);

        constexpr int SMD = NG * 4;  // 100 KB
        cudaFuncSetAttribute(div_kernel, cudaFuncAttributeMaxDynamicSharedMemorySize, SMD);
        div_kernel<<<NB, 512, SMD>>>(out, exph, denomT, idx);
    }
}

// round 15
// speedup vs baseline: 1.4414x; 1.0292x over previous
#include <cuda_runtime.h>
#include <cuda_fp16.h>
#include <math.h>
#include <stdint.h>

#define NB   256
#define DIN  5000
#define NH1  2048
#define NH2  1024
#define NISO 100000
#define NG   25000

// ---------------- scratch (static device arrays; allocation-free) ----------------
__device__ float  g_h1[NB * NH1];
__device__ float  g_h2[NB * NH2];
__device__ __half g_h2h[NB * NH2];
__device__ float  g_denom2[NG * NB];   // [gene][batch]
__device__ float  g_denomT[NB * NG];   // [batch][gene]
__device__ __half g_exph[(size_t)NB * NISO];  // fp16 exp-logit staging (51.2 MB)

// ---------------- helpers ----------------
__device__ __forceinline__ void cp16(void* s, const void* g, bool pred) {
    uint32_t sa = (uint32_t)__cvta_generic_to_shared(s);
    int sz = pred ? 16 : 0;
    asm volatile("cp.async.cg.shared.global [%0], [%1], 16, %2;\n"
                 :: "r"(sa), "l"(g), "r"(sz) : "memory");
}

__device__ __forceinline__ void mma_f16(float* c, const uint32_t* a, const uint32_t* b) {
    asm volatile(
        "mma.sync.aligned.m16n8k16.row.col.f32.f16.f16.f32 "
        "{%0,%1,%2,%3}, {%4,%5,%6,%7}, {%8,%9}, {%0,%1,%2,%3};\n"
        : "+f"(c[0]), "+f"(c[1]), "+f"(c[2]), "+f"(c[3])
        : "r"(a[0]), "r"(a[1]), "r"(a[2]), "r"(a[3]), "r"(b[0]), "r"(b[1]));
}

// pack two f32 -> f16x2 register {lo=first, hi=second}
__device__ __forceinline__ uint32_t pack_f16(float lo, float hi) {
    uint32_t r;
    asm("cvt.rn.f16x2.f32 %0, %1, %2;" : "=r"(r) : "f"(hi), "f"(lo));
    return r;
}

// ================= GEMM3: fp16 mma.sync (f32 acc), BM=256, BN=128, BK=32 =================
// grid = ceil(NISO/128) = 782. A = g_h2h fp16; B = W3 fp32 converted in regs.
// Epilogue (single pass): bias + exp -> smem staging (256 rows) -> red.v4 denom + fp16 stores.
__global__ void __launch_bounds__(512, 1)
gemm3_fp16_kernel(const __half* __restrict__ A, const float* __restrict__ W,
                  const float* __restrict__ bias, const int* __restrict__ idx,
                  __half* __restrict__ expH, float* __restrict__ denom2)
{
    constexpr int S   = 4;
    constexpr int BK  = 32;
    constexpr int TK  = NH2 / BK;    // 32
    constexpr int AP  = 40;          // halfs per A row (32 + 8 pad) -> conflict-free
    constexpr int BNP = 132;         // floats per B row (128 + 4 pad)
    constexpr int ASTG = 256 * AP;   // halfs per A stage (20480 B)
    constexpr int BSTG = BK * BNP;   // floats per B stage (16896 B)

    extern __shared__ char sm3[];
    __half* sA  = (__half*)sm3;
    float*  sB  = (float*)(sm3 + S * ASTG * 2);
    float*  sEp = (float*)sm3;       // epilogue reuse: 256 x 132 floats (135168 B)

    const int tid  = threadIdx.x;
    const int warp = tid >> 5;
    const int lane = tid & 31;
    const int g    = lane >> 2;
    const int tig  = lane & 3;
    const int wm   = (warp >> 2) * 64;   // 0,64,128,192
    const int wn   = (warp & 3) * 32;    // 0,32,64,96
    const int bn   = blockIdx.x * 128;

    float acc[4][4][4];
#pragma unroll
    for (int i = 0; i < 4; ++i)
#pragma unroll
        for (int j = 0; j < 4; ++j)
#pragma unroll
            for (int r = 0; r < 4; ++r) acc[i][j][r] = 0.f;

    auto load_tile = [&](int t) {
        const int st = t & (S - 1);
        const int k0 = t * BK;
#pragma unroll
        for (int i = 0; i < 2; ++i) {   // A: 256 rows x 4 chunks of 16B
            int ch = tid + i * 512;
            int row = ch >> 2, c = ch & 3;
            cp16(sA + st * ASTG + row * AP + c * 8,
                 A + (size_t)row * NH2 + k0 + c * 8, true);
        }
#pragma unroll
        for (int i = 0; i < 2; ++i) {   // B: 32 rows x 32 chunks of 16B
            int ch = tid + i * 512;
            int r = ch >> 5, c = ch & 31;
            int col = bn + c * 4;
            bool v = col < NISO;
            cp16(sB + st * BSTG + r * BNP + c * 4,
                 W + (size_t)(k0 + r) * NISO + (v ? col : 0), v);
        }
        asm volatile("cp.async.commit_group;\n" ::: "memory");
    };

    load_tile(0); load_tile(1); load_tile(2);

    for (int t = 0; t < TK; ++t) {
        asm volatile("cp.async.wait_group 2;\n" ::: "memory");
        __syncthreads();

        if (t + 3 < TK) load_tile(t + 3);
        else asm volatile("cp.async.commit_group;\n" ::: "memory");

        const int st = t & (S - 1);
        const __half* a = sA + st * ASTG;
        const float*  b = sB + st * BSTG;

#pragma unroll
        for (int ks = 0; ks < 2; ++ks) {
            uint32_t af[4][4];
#pragma unroll
            for (int mt = 0; mt < 4; ++mt) {
                const uint32_t* ap0 = (const uint32_t*)(a + (wm + mt * 16 + g) * AP) + ks * 8;
                const uint32_t* ap1 = (const uint32_t*)(a + (wm + mt * 16 + g + 8) * AP) + ks * 8;
                af[mt][0] = ap0[tig];
                af[mt][1] = ap1[tig];
                af[mt][2] = ap0[tig + 4];
                af[mt][3] = ap1[tig + 4];
            }
            uint32_t bf[4][2];
#pragma unroll
            for (int nt = 0; nt < 4; ++nt) {
                const float* bp = b + (size_t)ks * 16 * BNP + wn + nt * 8 + g;
                float f0 = bp[(2 * tig) * BNP];
                float f1 = bp[(2 * tig + 1) * BNP];
                float f2 = bp[(2 * tig + 8) * BNP];
                float f3 = bp[(2 * tig + 9) * BNP];
                bf[nt][0] = pack_f16(f0, f1);
                bf[nt][1] = pack_f16(f2, f3);
            }
#pragma unroll
            for (int mt = 0; mt < 4; ++mt)
#pragma unroll
                for (int nt = 0; nt < 4; ++nt)
                    mma_f16(acc[mt][nt], af[mt], bf[nt]);
        }
    }

    __syncthreads();   // compute done; reuse smem

    // ---- single-pass epilogue: stage exp(logit+bias) for all 256 rows ----
#pragma unroll
    for (int nt = 0; nt < 4; ++nt) {
        int cl0  = wn + nt * 8 + tig * 2;
        int col0 = bn + cl0;
        float bia0 = (col0 < NISO)     ? bias[col0]     : 0.f;
        float bia1 = (col0 + 1 < NISO) ? bias[col0 + 1] : 0.f;
#pragma unroll
        for (int mt = 0; mt < 4; ++mt) {
            int rl = wm + mt * 16 + g;
#pragma unroll
            for (int r = 0; r < 4; ++r) {
                int rr  = rl + ((r >= 2) ? 8 : 0);
                int cl  = cl0 + (r & 1);
                int col = col0 + (r & 1);
                if (col < NISO)
                    sEp[rr * BNP + cl] =
                        __expf(acc[mt][nt][r] + ((r & 1) ? bia1 : bia0));
            }
        }
    }
    __syncthreads();

    // (a) denom red.v4: 128 cols x 256 rows (64 v4-groups per col, 16 per thread)
    {
        int c  = tid & 127;
        int rq = tid >> 7;               // 0..3
        int col = bn + c;
        if (col < NISO) {
            int gene = idx[col];
            float* dst = denom2 + (size_t)gene * NB;
#pragma unroll
            for (int p = 0; p < 16; ++p) {
                int r = (p * 4 + rq) * 4;
                float v0 = sEp[(r + 0) * BNP + c];
                float v1 = sEp[(r + 1) * BNP + c];
                float v2 = sEp[(r + 2) * BNP + c];
                float v3 = sEp[(r + 3) * BNP + c];
                asm volatile("red.global.add.v4.f32 [%0], {%1, %2, %3, %4};"
                             :: "l"(dst + r), "f"(v0), "f"(v1), "f"(v2), "f"(v3)
                             : "memory");
            }
        }
    }
    // (b) coalesced fp16 numerator stores: 256 rows x 32 groups of 4 cols (8B)
#pragma unroll
    for (int i = 0; i < 16; ++i) {
        int id = tid + i * 512;
        int rr = id >> 5, c4 = id & 31;
        int col = bn + c4 * 4;
        if (col < NISO) {
            float4 v = *(const float4*)&sEp[rr * BNP + c4 * 4];
            uint2 u;
            u.x = pack_f16(v.x, v.y);
            u.y = pack_f16(v.z, v.w);
            *(uint2*)&expH[(size_t)rr * NISO + col] = u;
        }
    }
}

// ================= Layers 1 & 2: fp16 GEMM =================
template<int BM, int BN, int WM, int WN>
__global__ void __launch_bounds__(256)
gemm_fp16_l12_kernel(const float* __restrict__ A, const float* __restrict__ W,
                     const float* __restrict__ bias, float* __restrict__ out,
                     int M, int N, int K)
{
    constexpr int S   = 3;
    constexpr int BK  = 16;
    constexpr int BKP = BK + 4;
    constexpr int BNP = BN + 4;
    constexpr int WARPS_N = BN / WN;
    constexpr int MT  = WM / 16;
    constexpr int NT  = WN / 8;
    constexpr int ACH = BM * BK / 4;
    constexpr int BCH = BK * BN / 4;

    extern __shared__ float smem12[];
    float* sAb = smem12;
    float* sBb = smem12 + S * BM * BKP;

    const int tid  = threadIdx.x;
    const int warp = tid >> 5;
    const int lane = tid & 31;
    const int gid  = lane >> 2;
    const int tig  = lane & 3;
    const int wm   = (warp / WARPS_N) * WM;
    const int wn   = (warp % WARPS_N) * WN;
    const int bm   = blockIdx.y * BM;
    const int bn   = blockIdx.x * BN;

    const int T = (K + BK - 1) / BK;

    float acc[MT][NT][4];
#pragma unroll
    for (int i = 0; i < MT; ++i)
#pragma unroll
        for (int j = 0; j < NT; ++j)
#pragma unroll
            for (int r = 0; r < 4; ++r) acc[i][j][r] = 0.f;

    auto load_tile = [&](int t, int stage) {
        const int k0 = t * BK;
        float* sa = sAb + stage * BM * BKP;
        float* sb = sBb + stage * BK * BNP;
#pragma unroll
        for (int i = 0; i < (ACH + 255) / 256; ++i) {
            int c = tid + i * 256;
            if (ACH % 256 == 0 || c < ACH) {
                int row = c / 4;
                int cc  = c & 3;
                int kk  = k0 + cc * 4;
                int kc  = kk < K ? kk : 0;
                cp16(sa + row * BKP + cc * 4, A + (size_t)(bm + row) * K + kc, kk < K);
            }
        }
#pragma unroll
        for (int i = 0; i < (BCH + 255) / 256; ++i) {
            int c = tid + i * 256;
            if (BCH % 256 == 0 || c < BCH) {
                int row = c / (BN / 4);
                int cc  = c % (BN / 4);
                int col = bn + cc * 4;
                int kk  = k0 + row;
                bool p  = (kk < K) && (col < N);
                int kc  = kk < K ? kk : 0;
                int cl  = col < N ? col : 0;
                cp16(sb + row * BNP + cc * 4, W + (size_t)kc * N + cl, p);
            }
        }
        asm volatile("cp.async.commit_group;\n" ::: "memory");
    };

    load_tile(0, 0);
    if (T > 1) load_tile(1, 1); else asm volatile("cp.async.commit_group;\n" ::: "memory");

    for (int t = 0; t < T; ++t) {
        asm volatile("cp.async.wait_group 1;\n" ::: "memory");
        __syncthreads();
        if (t + 2 < T) load_tile(t + 2, (t + 2) % S);
        else asm volatile("cp.async.commit_group;\n" ::: "memory");

        const float* a = sAb + (t % S) * BM * BKP;
        const float* b = sBb + (t % S) * BK * BNP;

        uint32_t ah[MT][4];
#pragma unroll
        for (int mt = 0; mt < MT; ++mt) {
            const float* ap0 = a + (size_t)(wm + mt * 16 + gid) * BKP;
            const float* ap1 = ap0 + 8 * BKP;
            float2 x0 = *(const float2*)(ap0 + 2 * tig);
            float2 x1 = *(const float2*)(ap1 + 2 * tig);
            float2 x2 = *(const float2*)(ap0 + 2 * tig + 8);
            float2 x3 = *(const float2*)(ap1 + 2 * tig + 8);
            ah[mt][0] = pack_f16(x0.x, x0.y);
            ah[mt][1] = pack_f16(x1.x, x1.y);
            ah[mt][2] = pack_f16(x2.x, x2.y);
            ah[mt][3] = pack_f16(x3.x, x3.y);
        }
        uint32_t bh[NT][2];
#pragma unroll
        for (int nt = 0; nt < NT; ++nt) {
            const float* bp = b + wn + nt * 8 + gid;
            float f0 = bp[(2 * tig) * BNP];
            float f1 = bp[(2 * tig + 1) * BNP];
            float f2 = bp[(2 * tig + 8) * BNP];
            float f3 = bp[(2 * tig + 9) * BNP];
            bh[nt][0] = pack_f16(f0, f1);
            bh[nt][1] = pack_f16(f2, f3);
        }
#pragma unroll
        for (int mt = 0; mt < MT; ++mt)
#pragma unroll
            for (int nt = 0; nt < NT; ++nt)
                mma_f16(acc[mt][nt], ah[mt], bh[nt]);
    }

#pragma unroll
    for (int nt = 0; nt < NT; ++nt) {
        int col0 = bn + wn + nt * 8 + tig * 2;
        float bia0 = (col0 < N)     ? bias[col0]     : 0.f;
        float bia1 = (col0 + 1 < N) ? bias[col0 + 1] : 0.f;
#pragma unroll
        for (int mt = 0; mt < MT; ++mt) {
            int row0 = bm + wm + mt * 16 + gid;
#pragma unroll
            for (int r = 0; r < 4; ++r) {
                int row = row0 + ((r >= 2) ? 8 : 0);
                int col = col0 + (r & 1);
                if (col < N)
                    out[(size_t)row * N + col] = acc[mt][nt][r] + ((r & 1) ? bia1 : bia0);
            }
        }
    }
}

// ---------------- LayerNorm + exact GELU, 512 threads, float4-vectorized ----------------
template<typename OutT, bool ZERO>
__global__ void __launch_bounds__(512)
ln_gelu_kernel(const float* __restrict__ in, OutT* __restrict__ outp,
               const float* __restrict__ g,
               const float* __restrict__ beta, int H,
               float* __restrict__ zbuf)
{
    int row = blockIdx.x;
    if (ZERO) {
        float4* z = (float4*)(zbuf + (size_t)row * NG);
        for (int i = threadIdx.x; i < NG / 4; i += blockDim.x)
            z[i] = make_float4(0.f, 0.f, 0.f, 0.f);
    }
    const float4* x4 = (const float4*)(in + (size_t)row * H);
    const int H4 = H / 4;
    float s = 0.f, ss = 0.f;
    for (int i = threadIdx.x; i < H4; i += 512) {
        float4 v = x4[i];
        s  += v.x + v.y + v.z + v.w;
        ss += v.x * v.x + v.y * v.y + v.z * v.z + v.w * v.w;
    }
    __shared__ float sh[2][16];
#pragma unroll
    for (int o = 16; o > 0; o >>= 1) {
        s  += __shfl_xor_sync(0xffffffffu, s, o);
        ss += __shfl_xor_sync(0xffffffffu, ss, o);
    }
    int w = threadIdx.x >> 5;
    if ((threadIdx.x & 31) == 0) { sh[0][w] = s; sh[1][w] = ss; }
    __syncthreads();
    float ts = 0.f, tss = 0.f;
#pragma unroll
    for (int i = 0; i < 16; ++i) { ts += sh[0][i]; tss += sh[1][i]; }
    float mu   = ts / (float)H;
    float var  = tss / (float)H - mu * mu;
    float rstd = rsqrtf(var + 1e-5f);
    const float4* g4  = (const float4*)g;
    const float4* be4 = (const float4*)beta;
    for (int i = threadIdx.x; i < H4; i += 512) {
        float4 v = x4[i];
        float4 gg = g4[i];
        float4 bb = be4[i];
        float o0 = (v.x - mu) * rstd * gg.x + bb.x;
        float o1 = (v.y - mu) * rstd * gg.y + bb.y;
        float o2 = (v.z - mu) * rstd * gg.z + bb.z;
        float o3 = (v.w - mu) * rstd * gg.w + bb.w;
        o0 = 0.5f * o0 * (1.0f + erff(o0 * 0.70710678118654752f));
        o1 = 0.5f * o1 * (1.0f + erff(o1 * 0.70710678118654752f));
        o2 = 0.5f * o2 * (1.0f + erff(o2 * 0.70710678118654752f));
        o3 = 0.5f * o3 * (1.0f + erff(o3 * 0.70710678118654752f));
        if constexpr (sizeof(OutT) == 2) {
            uint2 u;
            u.x = pack_f16(o0, o1);
            u.y = pack_f16(o2, o3);
            *(uint2*)&outp[(size_t)row * H + i * 4] = u;
        } else {
            *(float4*)&outp[(size_t)row * H + i * 4] = make_float4(o0, o1, o2, o3);
        }
    }
}

// ---------------- denom transpose: [gene][batch] -> [batch][gene] ----------------
__global__ void transpose_kernel(const float* __restrict__ in, float* __restrict__ out)
{
    __shared__ float t[32][33];
    int g0 = blockIdx.x * 32, b0 = blockIdx.y * 32;
#pragma unroll
    for (int dy = 0; dy < 32; dy += 8) {
        int gg = g0 + threadIdx.y + dy;
        if (gg < NG) t[threadIdx.y + dy][threadIdx.x] = in[(size_t)gg * NB + b0 + threadIdx.x];
    }
    __syncthreads();
#pragma unroll
    for (int dy = 0; dy < 32; dy += 8) {
        int gg = g0 + threadIdx.x;
        int bb = b0 + threadIdx.y + dy;
        if (gg < NG) out[(size_t)bb * NG + gg] = t[threadIdx.x][threadIdx.y + dy];
    }
}

// ---------------- normalize: fp16 numerator * smem-resident reciprocal ----------------
__global__ void __launch_bounds__(512)
div_kernel(float* __restrict__ out, const __half* __restrict__ expH,
           const float* __restrict__ denomT, const int* __restrict__ idx)
{
    extern __shared__ float sd[];      // NG floats = 100 KB (reciprocals)
    int b = blockIdx.x;
    const float4* dr = (const float4*)(denomT + (size_t)b * NG);
    for (int i = threadIdx.x; i < NG / 4; i += blockDim.x) {
        float4 d = dr[i];
        float4 rc;
        rc.x = 1.0f / fmaxf(d.x, 1e-8f);
        rc.y = 1.0f / fmaxf(d.y, 1e-8f);
        rc.z = 1.0f / fmaxf(d.z, 1e-8f);
        rc.w = 1.0f / fmaxf(d.w, 1e-8f);
        ((float4*)sd)[i] = rc;
    }
    __syncthreads();
    float4* orow = (float4*)(out + (size_t)b * NISO);
    const uint2* erow = (const uint2*)(expH + (size_t)b * NISO);
    const int4* gi = (const int4*)idx;
    for (int i = threadIdx.x; i < NISO / 4; i += blockDim.x) {
        uint2 u = erow[i];
        float2 e01 = __half22float2(*(const __half2*)&u.x);
        float2 e23 = __half22float2(*(const __half2*)&u.y);
        int4 g4 = gi[i];
        float4 v;
        v.x = e01.x * sd[g4.x];
        v.y = e01.y * sd[g4.y];
        v.z = e23.x * sd[g4.z];
        v.w = e23.y * sd[g4.w];
        orow[i] = v;
    }
}

extern "C" void kernel_launch(void* const* d_in, const int* in_sizes, int n_in,
                              void* d_out, int out_size)
{
    const float* x   = (const float*)d_in[0];
    const int*   idx = (const int*)  d_in[1];
    const float* W1  = (const float*)d_in[2];
    const float* b1  = (const float*)d_in[3];
    const float* g1  = (const float*)d_in[4];
    const float* be1 = (const float*)d_in[5];
    const float* W2  = (const float*)d_in[6];
    const float* b2  = (const float*)d_in[7];
    const float* g2  = (const float*)d_in[8];
    const float* be2 = (const float*)d_in[9];
    const float* W3  = (const float*)d_in[10];
    const float* b3  = (const float*)d_in[11];
    float* out = (float*)d_out;

    float *h1, *h2, *denom2, *denomT;
    __half *h2h, *exph;
    cudaGetSymbolAddress((void**)&h1, g_h1);
    cudaGetSymbolAddress((void**)&h2, g_h2);
    cudaGetSymbolAddress((void**)&h2h, g_h2h);
    cudaGetSymbolAddress((void**)&denom2, g_denom2);
    cudaGetSymbolAddress((void**)&denomT, g_denomT);
    cudaGetSymbolAddress((void**)&exph, g_exph);

    // ---- Layer 1: x @ W1 (fp16), 256 CTAs ----
    {
        constexpr int BM = 32, BN = 64;
        constexpr int SM = 3 * (BM * 20 + 16 * (BN + 4)) * 4;
        auto k = gemm_fp16_l12_kernel<BM, BN, 16, 16>;
        cudaFuncSetAttribute(k, cudaFuncAttributeMaxDynamicSharedMemorySize, SM);
        dim3 grid(NH1 / BN, NB / BM);
        k<<<grid, 256, SM>>>(x, W1, b1, h1, NB, NH1, DIN);
    }
    ln_gelu_kernel<float, false><<<NB, 512>>>(h1, h1, g1, be1, NH1, nullptr);

    // ---- Layer 2: h1 @ W2 (fp16) ----
    {
        constexpr int BM = 32, BN = 64;
        constexpr int SM = 3 * (BM * 20 + 16 * (BN + 4)) * 4;
        auto k = gemm_fp16_l12_kernel<BM, BN, 16, 16>;
        cudaFuncSetAttribute(k, cudaFuncAttributeMaxDynamicSharedMemorySize, SM);
        dim3 grid(NH2 / BN, NB / BM);
        k<<<grid, 256, SM>>>(h1, W2, b2, h2, NB, NH2, NH1);
    }
    // LN2 also zeros denom2
    ln_gelu_kernel<__half, true><<<NB, 512>>>(h2, h2h, g2, be2, NH2, denom2);

    // ---- Layer 3: fp16 mma GEMM, BM=256 x BN=128, BK=32, single-pass epilogue ----
    {
        constexpr int ASTG = 256 * 40;            // halfs
        constexpr int BSTG = 32 * 132;            // floats
        constexpr int SM3  = 4 * (ASTG * 2 + BSTG * 4);  // 149504 B
        cudaFuncSetAttribute(gemm3_fp16_kernel, cudaFuncAttributeMaxDynamicSharedMemorySize, SM3);
        gemm3_fp16_kernel<<<(NISO + 127) / 128, 512, SM3>>>(h2h, W3, b3, idx, exph, denom2);
    }

    // ---- transpose denom, then normalize fp16 numerators with reciprocal rows ----
    {
        dim3 grid((NG + 31) / 32, NB / 32);
        transpose_kernel<<<grid, dim3(32, 8)>>>(denom2, denomT);

        constexpr int SMD = NG * 4;  // 100 KB
        cudaFuncSetAttribute(div_kernel, cudaFuncAttributeMaxDynamicSharedMemorySize, SMD);
        div_kernel<<<NB, 512, SMD>>>(out, exph, denomT, idx);
    }
}

// round 16
// speedup vs baseline: 1.5018x; 1.0419x over previous
#include <cuda_runtime.h>
#include <cuda_fp16.h>
#include <math.h>
#include <stdint.h>

#define NB   256
#define DIN  5000
#define NH1  2048
#define NH2  1024
#define NISO 100000
#define NG   25000

// ---------------- scratch (static device arrays; allocation-free) ----------------
__device__ float  g_h1[NB * NH1];
__device__ float  g_h2[NB * NH2];
__device__ __half g_h2h[NB * NH2];
__device__ float  g_denom2[NG * NB];   // [gene][batch]
__device__ float  g_denomT[NB * NG];   // [batch][gene]
__device__ __half g_exph[(size_t)NB * NISO];  // fp16 exp-logit staging (51.2 MB)

// ---------------- helpers ----------------
__device__ __forceinline__ void cp16(void* s, const void* g, bool pred) {
    uint32_t sa = (uint32_t)__cvta_generic_to_shared(s);
    int sz = pred ? 16 : 0;
    asm volatile("cp.async.cg.shared.global [%0], [%1], 16, %2;\n"
                 :: "r"(sa), "l"(g), "r"(sz) : "memory");
}

__device__ __forceinline__ void mma_f16(float* c, const uint32_t* a, const uint32_t* b) {
    asm volatile(
        "mma.sync.aligned.m16n8k16.row.col.f32.f16.f16.f32 "
        "{%0,%1,%2,%3}, {%4,%5,%6,%7}, {%8,%9}, {%0,%1,%2,%3};\n"
        : "+f"(c[0]), "+f"(c[1]), "+f"(c[2]), "+f"(c[3])
        : "r"(a[0]), "r"(a[1]), "r"(a[2]), "r"(a[3]), "r"(b[0]), "r"(b[1]));
}

// pack two f32 -> f16x2 register {lo=first, hi=second}
__device__ __forceinline__ uint32_t pack_f16(float lo, float hi) {
    uint32_t r;
    asm("cvt.rn.f16x2.f32 %0, %1, %2;" : "=r"(r) : "f"(hi), "f"(lo));
    return r;
}

// ================= GEMM3: fp16 mma.sync (f32 acc), BM=256, BN=128, BK=32 =================
// grid = ceil(NISO/128) = 782. A = g_h2h fp16; B = W3 fp32 converted in regs.
// Epilogue (single pass): bias + exp -> smem staging (256 rows) -> red.v4 denom + fp16 stores.
__global__ void __launch_bounds__(512, 1)
gemm3_fp16_kernel(const __half* __restrict__ A, const float* __restrict__ W,
                  const float* __restrict__ bias, const int* __restrict__ idx,
                  __half* __restrict__ expH, float* __restrict__ denom2)
{
    constexpr int S   = 4;
    constexpr int BK  = 32;
    constexpr int TK  = NH2 / BK;    // 32
    constexpr int AP  = 40;          // halfs per A row (32 + 8 pad) -> conflict-free
    constexpr int BNP = 132;         // floats per B row (128 + 4 pad)
    constexpr int ASTG = 256 * AP;   // halfs per A stage (20480 B)
    constexpr int BSTG = BK * BNP;   // floats per B stage (16896 B)

    extern __shared__ char sm3[];
    __half* sA  = (__half*)sm3;
    float*  sB  = (float*)(sm3 + S * ASTG * 2);
    float*  sEp = (float*)sm3;       // epilogue reuse: 256 x 132 floats (135168 B)

    const int tid  = threadIdx.x;
    const int warp = tid >> 5;
    const int lane = tid & 31;
    const int g    = lane >> 2;
    const int tig  = lane & 3;
    const int wm   = (warp >> 2) * 64;   // 0,64,128,192
    const int wn   = (warp & 3) * 32;    // 0,32,64,96
    const int bn   = blockIdx.x * 128;

    float acc[4][4][4];
#pragma unroll
    for (int i = 0; i < 4; ++i)
#pragma unroll
        for (int j = 0; j < 4; ++j)
#pragma unroll
            for (int r = 0; r < 4; ++r) acc[i][j][r] = 0.f;

    auto load_tile = [&](int t) {
        const int st = t & (S - 1);
        const int k0 = t * BK;
#pragma unroll
        for (int i = 0; i < 2; ++i) {   // A: 256 rows x 4 chunks of 16B
            int ch = tid + i * 512;
            int row = ch >> 2, c = ch & 3;
            cp16(sA + st * ASTG + row * AP + c * 8,
                 A + (size_t)row * NH2 + k0 + c * 8, true);
        }
#pragma unroll
        for (int i = 0; i < 2; ++i) {   // B: 32 rows x 32 chunks of 16B
            int ch = tid + i * 512;
            int r = ch >> 5, c = ch & 31;
            int col = bn + c * 4;
            bool v = col < NISO;
            cp16(sB + st * BSTG + r * BNP + c * 4,
                 W + (size_t)(k0 + r) * NISO + (v ? col : 0), v);
        }
        asm volatile("cp.async.commit_group;\n" ::: "memory");
    };

    load_tile(0); load_tile(1); load_tile(2);

    for (int t = 0; t < TK; ++t) {
        asm volatile("cp.async.wait_group 2;\n" ::: "memory");
        __syncthreads();

        if (t + 3 < TK) load_tile(t + 3);
        else asm volatile("cp.async.commit_group;\n" ::: "memory");

        const int st = t & (S - 1);
        const __half* a = sA + st * ASTG;
        const float*  b = sB + st * BSTG;

#pragma unroll
        for (int ks = 0; ks < 2; ++ks) {
            uint32_t af[4][4];
#pragma unroll
            for (int mt = 0; mt < 4; ++mt) {
                const uint32_t* ap0 = (const uint32_t*)(a + (wm + mt * 16 + g) * AP) + ks * 8;
                const uint32_t* ap1 = (const uint32_t*)(a + (wm + mt * 16 + g + 8) * AP) + ks * 8;
                af[mt][0] = ap0[tig];
                af[mt][1] = ap1[tig];
                af[mt][2] = ap0[tig + 4];
                af[mt][3] = ap1[tig + 4];
            }
            uint32_t bf[4][2];
#pragma unroll
            for (int nt = 0; nt < 4; ++nt) {
                const float* bp = b + (size_t)ks * 16 * BNP + wn + nt * 8 + g;
                float f0 = bp[(2 * tig) * BNP];
                float f1 = bp[(2 * tig + 1) * BNP];
                float f2 = bp[(2 * tig + 8) * BNP];
                float f3 = bp[(2 * tig + 9) * BNP];
                bf[nt][0] = pack_f16(f0, f1);
                bf[nt][1] = pack_f16(f2, f3);
            }
#pragma unroll
            for (int mt = 0; mt < 4; ++mt)
#pragma unroll
                for (int nt = 0; nt < 4; ++nt)
                    mma_f16(acc[mt][nt], af[mt], bf[nt]);
        }
    }

    __syncthreads();   // compute done; reuse smem

    // ---- single-pass epilogue: stage exp(logit+bias) for all 256 rows ----
#pragma unroll
    for (int nt = 0; nt < 4; ++nt) {
        int cl0  = wn + nt * 8 + tig * 2;
        int col0 = bn + cl0;
        float bia0 = (col0 < NISO)     ? bias[col0]     : 0.f;
        float bia1 = (col0 + 1 < NISO) ? bias[col0 + 1] : 0.f;
#pragma unroll
        for (int mt = 0; mt < 4; ++mt) {
            int rl = wm + mt * 16 + g;
#pragma unroll
            for (int r = 0; r < 4; ++r) {
                int rr  = rl + ((r >= 2) ? 8 : 0);
                int cl  = cl0 + (r & 1);
                int col = col0 + (r & 1);
                if (col < NISO)
                    sEp[rr * BNP + cl] =
                        __expf(acc[mt][nt][r] + ((r & 1) ? bia1 : bia0));
            }
        }
    }
    __syncthreads();

    // (a) denom red.v4: 128 cols x 256 rows (64 v4-groups per col, 16 per thread)
    {
        int c  = tid & 127;
        int rq = tid >> 7;               // 0..3
        int col = bn + c;
        if (col < NISO) {
            int gene = idx[col];
            float* dst = denom2 + (size_t)gene * NB;
#pragma unroll
            for (int p = 0; p < 16; ++p) {
                int r = (p * 4 + rq) * 4;
                float v0 = sEp[(r + 0) * BNP + c];
                float v1 = sEp[(r + 1) * BNP + c];
                float v2 = sEp[(r + 2) * BNP + c];
                float v3 = sEp[(r + 3) * BNP + c];
                asm volatile("red.global.add.v4.f32 [%0], {%1, %2, %3, %4};"
                             :: "l"(dst + r), "f"(v0), "f"(v1), "f"(v2), "f"(v3)
                             : "memory");
            }
        }
    }
    // (b) coalesced fp16 numerator stores: 256 rows x 32 groups of 4 cols (8B)
#pragma unroll
    for (int i = 0; i < 16; ++i) {
        int id = tid + i * 512;
        int rr = id >> 5, c4 = id & 31;
        int col = bn + c4 * 4;
        if (col < NISO) {
            float4 v = *(const float4*)&sEp[rr * BNP + c4 * 4];
            uint2 u;
            u.x = pack_f16(v.x, v.y);
            u.y = pack_f16(v.z, v.w);
            *(uint2*)&expH[(size_t)rr * NISO + col] = u;
        }
    }
}

// ================= Layers 1 & 2: fp16 GEMM (templated BK) =================
template<int BM, int BN, int WM, int WN, int BK>
__global__ void __launch_bounds__(256)
gemm_fp16_l12_kernel(const float* __restrict__ A, const float* __restrict__ W,
                     const float* __restrict__ bias, float* __restrict__ out,
                     int M, int N, int K)
{
    constexpr int S   = 3;
    constexpr int BKP = BK + 4;
    constexpr int BNP = BN + 4;
    constexpr int WARPS_N = BN / WN;
    constexpr int MT  = WM / 16;
    constexpr int NT  = WN / 8;
    constexpr int KS  = BK / 16;
    constexpr int ACH = BM * BK / 4;
    constexpr int BCH = BK * BN / 4;
    constexpr int AKC = BK / 4;       // 16B chunks per A row

    extern __shared__ float smem12[];
    float* sAb = smem12;
    float* sBb = smem12 + S * BM * BKP;

    const int tid  = threadIdx.x;
    const int warp = tid >> 5;
    const int lane = tid & 31;
    const int gid  = lane >> 2;
    const int tig  = lane & 3;
    const int wm   = (warp / WARPS_N) * WM;
    const int wn   = (warp % WARPS_N) * WN;
    const int bm   = blockIdx.y * BM;
    const int bn   = blockIdx.x * BN;

    const int T = (K + BK - 1) / BK;

    float acc[MT][NT][4];
#pragma unroll
    for (int i = 0; i < MT; ++i)
#pragma unroll
        for (int j = 0; j < NT; ++j)
#pragma unroll
            for (int r = 0; r < 4; ++r) acc[i][j][r] = 0.f;

    auto load_tile = [&](int t, int stage) {
        const int k0 = t * BK;
        float* sa = sAb + stage * BM * BKP;
        float* sb = sBb + stage * BK * BNP;
#pragma unroll
        for (int i = 0; i < (ACH + 255) / 256; ++i) {
            int c = tid + i * 256;
            if (ACH % 256 == 0 || c < ACH) {
                int row = c / AKC;
                int cc  = c % AKC;
                int kk  = k0 + cc * 4;
                int kc  = kk < K ? kk : 0;
                cp16(sa + row * BKP + cc * 4, A + (size_t)(bm + row) * K + kc, kk < K);
            }
        }
#pragma unroll
        for (int i = 0; i < (BCH + 255) / 256; ++i) {
            int c = tid + i * 256;
            if (BCH % 256 == 0 || c < BCH) {
                int row = c / (BN / 4);
                int cc  = c % (BN / 4);
                int col = bn + cc * 4;
                int kk  = k0 + row;
                bool p  = (kk < K) && (col < N);
                int kc  = kk < K ? kk : 0;
                int cl  = col < N ? col : 0;
                cp16(sb + row * BNP + cc * 4, W + (size_t)kc * N + cl, p);
            }
        }
        asm volatile("cp.async.commit_group;\n" ::: "memory");
    };

    load_tile(0, 0);
    if (T > 1) load_tile(1, 1); else asm volatile("cp.async.commit_group;\n" ::: "memory");

    for (int t = 0; t < T; ++t) {
        asm volatile("cp.async.wait_group 1;\n" ::: "memory");
        __syncthreads();
        if (t + 2 < T) load_tile(t + 2, (t + 2) % S);
        else asm volatile("cp.async.commit_group;\n" ::: "memory");

        const float* a = sAb + (t % S) * BM * BKP;
        const float* b = sBb + (t % S) * BK * BNP;

#pragma unroll
        for (int ksb = 0; ksb < KS; ++ksb) {
            uint32_t ah[MT][4];
#pragma unroll
            for (int mt = 0; mt < MT; ++mt) {
                const float* ap0 = a + (size_t)(wm + mt * 16 + gid) * BKP + ksb * 16;
                const float* ap1 = ap0 + 8 * BKP;
                float2 x0 = *(const float2*)(ap0 + 2 * tig);
                float2 x1 = *(const float2*)(ap1 + 2 * tig);
                float2 x2 = *(const float2*)(ap0 + 2 * tig + 8);
                float2 x3 = *(const float2*)(ap1 + 2 * tig + 8);
                ah[mt][0] = pack_f16(x0.x, x0.y);
                ah[mt][1] = pack_f16(x1.x, x1.y);
                ah[mt][2] = pack_f16(x2.x, x2.y);
                ah[mt][3] = pack_f16(x3.x, x3.y);
            }
            uint32_t bh[NT][2];
#pragma unroll
            for (int nt = 0; nt < NT; ++nt) {
                const float* bp = b + (size_t)ksb * 16 * BNP + wn + nt * 8 + gid;
                float f0 = bp[(2 * tig) * BNP];
                float f1 = bp[(2 * tig + 1) * BNP];
                float f2 = bp[(2 * tig + 8) * BNP];
                float f3 = bp[(2 * tig + 9) * BNP];
                bh[nt][0] = pack_f16(f0, f1);
                bh[nt][1] = pack_f16(f2, f3);
            }
#pragma unroll
            for (int mt = 0; mt < MT; ++mt)
#pragma unroll
                for (int nt = 0; nt < NT; ++nt)
                    mma_f16(acc[mt][nt], ah[mt], bh[nt]);
        }
    }

#pragma unroll
    for (int nt = 0; nt < NT; ++nt) {
        int col0 = bn + wn + nt * 8 + tig * 2;
        float bia0 = (col0 < N)     ? bias[col0]     : 0.f;
        float bia1 = (col0 + 1 < N) ? bias[col0 + 1] : 0.f;
#pragma unroll
        for (int mt = 0; mt < MT; ++mt) {
            int row0 = bm + wm + mt * 16 + gid;
#pragma unroll
            for (int r = 0; r < 4; ++r) {
                int row = row0 + ((r >= 2) ? 8 : 0);
                int col = col0 + (r & 1);
                if (col < N)
                    out[(size_t)row * N + col] = acc[mt][nt][r] + ((r & 1) ? bia1 : bia0);
            }
        }
    }
}

// ---------------- LayerNorm + exact GELU, 512 threads, float4-vectorized ----------------
template<typename OutT, bool ZERO>
__global__ void __launch_bounds__(512)
ln_gelu_kernel(const float* __restrict__ in, OutT* __restrict__ outp,
               const float* __restrict__ g,
               const float* __restrict__ beta, int H,
               float* __restrict__ zbuf)
{
    int row = blockIdx.x;
    if (ZERO) {
        float4* z = (float4*)(zbuf + (size_t)row * NG);
        for (int i = threadIdx.x; i < NG / 4; i += blockDim.x)
            z[i] = make_float4(0.f, 0.f, 0.f, 0.f);
    }
    const float4* x4 = (const float4*)(in + (size_t)row * H);
    const int H4 = H / 4;
    float s = 0.f, ss = 0.f;
    for (int i = threadIdx.x; i < H4; i += 512) {
        float4 v = x4[i];
        s  += v.x + v.y + v.z + v.w;
        ss += v.x * v.x + v.y * v.y + v.z * v.z + v.w * v.w;
    }
    __shared__ float sh[2][16];
#pragma unroll
    for (int o = 16; o > 0; o >>= 1) {
        s  += __shfl_xor_sync(0xffffffffu, s, o);
        ss += __shfl_xor_sync(0xffffffffu, ss, o);
    }
    int w = threadIdx.x >> 5;
    if ((threadIdx.x & 31) == 0) { sh[0][w] = s; sh[1][w] = ss; }
    __syncthreads();
    float ts = 0.f, tss = 0.f;
#pragma unroll
    for (int i = 0; i < 16; ++i) { ts += sh[0][i]; tss += sh[1][i]; }
    float mu   = ts / (float)H;
    float var  = tss / (float)H - mu * mu;
    float rstd = rsqrtf(var + 1e-5f);
    const float4* g4  = (const float4*)g;
    const float4* be4 = (const float4*)beta;
    for (int i = threadIdx.x; i < H4; i += 512) {
        float4 v = x4[i];
        float4 gg = g4[i];
        float4 bb = be4[i];
        float o0 = (v.x - mu) * rstd * gg.x + bb.x;
        float o1 = (v.y - mu) * rstd * gg.y + bb.y;
        float o2 = (v.z - mu) * rstd * gg.z + bb.z;
        float o3 = (v.w - mu) * rstd * gg.w + bb.w;
        o0 = 0.5f * o0 * (1.0f + erff(o0 * 0.70710678118654752f));
        o1 = 0.5f * o1 * (1.0f + erff(o1 * 0.70710678118654752f));
        o2 = 0.5f * o2 * (1.0f + erff(o2 * 0.70710678118654752f));
        o3 = 0.5f * o3 * (1.0f + erff(o3 * 0.70710678118654752f));
        if constexpr (sizeof(OutT) == 2) {
            uint2 u;
            u.x = pack_f16(o0, o1);
            u.y = pack_f16(o2, o3);
            *(uint2*)&outp[(size_t)row * H + i * 4] = u;
        } else {
            *(float4*)&outp[(size_t)row * H + i * 4] = make_float4(o0, o1, o2, o3);
        }
    }
}

// ---------------- denom transpose: [gene][batch] -> [batch][gene] ----------------
__global__ void transpose_kernel(const float* __restrict__ in, float* __restrict__ out)
{
    __shared__ float t[32][33];
    int g0 = blockIdx.x * 32, b0 = blockIdx.y * 32;
#pragma unroll
    for (int dy = 0; dy < 32; dy += 8) {
        int gg = g0 + threadIdx.y + dy;
        if (gg < NG) t[threadIdx.y + dy][threadIdx.x] = in[(size_t)gg * NB + b0 + threadIdx.x];
    }
    __syncthreads();
#pragma unroll
    for (int dy = 0; dy < 32; dy += 8) {
        int gg = g0 + threadIdx.x;
        int bb = b0 + threadIdx.y + dy;
        if (gg < NG) out[(size_t)bb * NG + gg] = t[threadIdx.x][threadIdx.y + dy];
    }
}

// ---------------- normalize: fp16 numerator * smem-resident reciprocal ----------------
__global__ void __launch_bounds__(512)
div_kernel(float* __restrict__ out, const __half* __restrict__ expH,
           const float* __restrict__ denomT, const int* __restrict__ idx)
{
    extern __shared__ float sd[];      // NG floats = 100 KB (reciprocals)
    int b = blockIdx.x;
    const float4* dr = (const float4*)(denomT + (size_t)b * NG);
    for (int i = threadIdx.x; i < NG / 4; i += blockDim.x) {
        float4 d = dr[i];
        float4 rc;
        rc.x = 1.0f / fmaxf(d.x, 1e-8f);
        rc.y = 1.0f / fmaxf(d.y, 1e-8f);
        rc.z = 1.0f / fmaxf(d.z, 1e-8f);
        rc.w = 1.0f / fmaxf(d.w, 1e-8f);
        ((float4*)sd)[i] = rc;
    }
    __syncthreads();
    float4* orow = (float4*)(out + (size_t)b * NISO);
    const uint2* erow = (const uint2*)(expH + (size_t)b * NISO);
    const int4* gi = (const int4*)idx;
    for (int i = threadIdx.x; i < NISO / 4; i += blockDim.x) {
        uint2 u = erow[i];
        float2 e01 = __half22float2(*(const __half2*)&u.x);
        float2 e23 = __half22float2(*(const __half2*)&u.y);
        int4 g4 = gi[i];
        float4 v;
        v.x = e01.x * sd[g4.x];
        v.y = e01.y * sd[g4.y];
        v.z = e23.x * sd[g4.z];
        v.w = e23.y * sd[g4.w];
        orow[i] = v;
    }
}

extern "C" void kernel_launch(void* const* d_in, const int* in_sizes, int n_in,
                              void* d_out, int out_size)
{
    const float* x   = (const float*)d_in[0];
    const int*   idx = (const int*)  d_in[1];
    const float* W1  = (const float*)d_in[2];
    const float* b1  = (const float*)d_in[3];
    const float* g1  = (const float*)d_in[4];
    const float* be1 = (const float*)d_in[5];
    const float* W2  = (const float*)d_in[6];
    const float* b2  = (const float*)d_in[7];
    const float* g2  = (const float*)d_in[8];
    const float* be2 = (const float*)d_in[9];
    const float* W3  = (const float*)d_in[10];
    const float* b3  = (const float*)d_in[11];
    float* out = (float*)d_out;

    float *h1, *h2, *denom2, *denomT;
    __half *h2h, *exph;
    cudaGetSymbolAddress((void**)&h1, g_h1);
    cudaGetSymbolAddress((void**)&h2, g_h2);
    cudaGetSymbolAddress((void**)&h2h, g_h2h);
    cudaGetSymbolAddress((void**)&denom2, g_denom2);
    cudaGetSymbolAddress((void**)&denomT, g_denomT);
    cudaGetSymbolAddress((void**)&exph, g_exph);

    // ---- Layer 1: x @ W1 (fp16, BK=16), 256 CTAs ----
    {
        constexpr int BM = 32, BN = 64, BK = 16;
        constexpr int SM = 3 * (BM * (BK + 4) + BK * (BN + 4)) * 4;
        auto k = gemm_fp16_l12_kernel<BM, BN, 16, 16, BK>;
        cudaFuncSetAttribute(k, cudaFuncAttributeMaxDynamicSharedMemorySize, SM);
        dim3 grid(NH1 / BN, NB / BM);
        k<<<grid, 256, SM>>>(x, W1, b1, h1, NB, NH1, DIN);
    }
    ln_gelu_kernel<float, false><<<NB, 512>>>(h1, h1, g1, be1, NH1, nullptr);

    // ---- Layer 2: h1 @ W2 (fp16, BK=32 -> 64 iters) ----
    {
        constexpr int BM = 32, BN = 64, BK = 32;
        constexpr int SM = 3 * (BM * (BK + 4) + BK * (BN + 4)) * 4;
        auto k = gemm_fp16_l12_kernel<BM, BN, 16, 16, BK>;
        cudaFuncSetAttribute(k, cudaFuncAttributeMaxDynamicSharedMemorySize, SM);
        dim3 grid(NH2 / BN, NB / BM);
        k<<<grid, 256, SM>>>(h1, W2, b2, h2, NB, NH2, NH1);
    }
    // LN2 also zeros denom2
    ln_gelu_kernel<__half, true><<<NB, 512>>>(h2, h2h, g2, be2, NH2, denom2);

    // ---- Layer 3: fp16 mma GEMM, BM=256 x BN=128, BK=32, single-pass epilogue ----
    {
        constexpr int ASTG = 256 * 40;            // halfs
        constexpr int BSTG = 32 * 132;            // floats
        constexpr int SM3  = 4 * (ASTG * 2 + BSTG * 4);  // 149504 B
        cudaFuncSetAttribute(gemm3_fp16_kernel, cudaFuncAttributeMaxDynamicSharedMemorySize, SM3);
        gemm3_fp16_kernel<<<(NISO + 127) / 128, 512, SM3>>>(h2h, W3, b3, idx, exph, denom2);
    }

    // ---- transpose denom, then normalize fp16 numerators with reciprocal rows ----
    {
        dim3 grid((NG + 31) / 32, NB / 32);
        transpose_kernel<<<grid, dim3(32, 8)>>>(denom2, denomT);

        constexpr int SMD = NG * 4;  // 100 KB
        cudaFuncSetAttribute(div_kernel, cudaFuncAttributeMaxDynamicSharedMemorySize, SMD);
        div_kernel<<<NB, 512, SMD>>>(out, exph, denomT, idx);
    }
}

// round 17
// speedup vs baseline: 1.5765x; 1.0497x over previous
#include <cuda_runtime.h>
#include <cuda_fp16.h>
#include <math.h>
#include <stdint.h>

#define NB   256
#define DIN  5000
#define NH1  2048
#define NH2  1024
#define NISO 100000
#define NG   25000

// ---------------- scratch (static device arrays; allocation-free) ----------------
__device__ float  g_h1[NB * NH1];
__device__ float  g_h2[NB * NH2];
__device__ __half g_h2h[NB * NH2];
__device__ float  g_denom2[NG * NB];   // [gene][batch]
__device__ float  g_denomT[NB * NG];   // [batch][gene]
__device__ __half g_exph[(size_t)NB * NISO];  // fp16 exp-logit staging (51.2 MB)

// ---------------- helpers ----------------
__device__ __forceinline__ void cp16(void* s, const void* g, bool pred) {
    uint32_t sa = (uint32_t)__cvta_generic_to_shared(s);
    int sz = pred ? 16 : 0;
    asm volatile("cp.async.cg.shared.global [%0], [%1], 16, %2;\n"
                 :: "r"(sa), "l"(g), "r"(sz) : "memory");
}

__device__ __forceinline__ void mma_f16(float* c, const uint32_t* a, const uint32_t* b) {
    asm volatile(
        "mma.sync.aligned.m16n8k16.row.col.f32.f16.f16.f32 "
        "{%0,%1,%2,%3}, {%4,%5,%6,%7}, {%8,%9}, {%0,%1,%2,%3};\n"
        : "+f"(c[0]), "+f"(c[1]), "+f"(c[2]), "+f"(c[3])
        : "r"(a[0]), "r"(a[1]), "r"(a[2]), "r"(a[3]), "r"(b[0]), "r"(b[1]));
}

// pack two f32 -> f16x2 register {lo=first, hi=second}
__device__ __forceinline__ uint32_t pack_f16(float lo, float hi) {
    uint32_t r;
    asm("cvt.rn.f16x2.f32 %0, %1, %2;" : "=r"(r) : "f"(hi), "f"(lo));
    return r;
}

// ================= GEMM3: fp16 mma.sync (f32 acc), BM=256, BN=128, BK=32 =================
// grid = ceil(NISO/128) = 782. A = g_h2h fp16; B = W3 fp32 converted in regs.
// Epilogue (single pass): bias + exp -> smem staging (256 rows) -> red.v4 denom + fp16 stores.
__global__ void __launch_bounds__(512, 1)
gemm3_fp16_kernel(const __half* __restrict__ A, const float* __restrict__ W,
                  const float* __restrict__ bias, const int* __restrict__ idx,
                  __half* __restrict__ expH, float* __restrict__ denom2)
{
    constexpr int S   = 4;
    constexpr int BK  = 32;
    constexpr int TK  = NH2 / BK;    // 32
    constexpr int AP  = 40;          // halfs per A row (32 + 8 pad) -> conflict-free
    constexpr int BNP = 132;         // floats per B row (128 + 4 pad)
    constexpr int ASTG = 256 * AP;   // halfs per A stage (20480 B)
    constexpr int BSTG = BK * BNP;   // floats per B stage (16896 B)

    extern __shared__ char sm3[];
    __half* sA  = (__half*)sm3;
    float*  sB  = (float*)(sm3 + S * ASTG * 2);
    float*  sEp = (float*)sm3;       // epilogue reuse: 256 x 132 floats (135168 B)

    const int tid  = threadIdx.x;
    const int warp = tid >> 5;
    const int lane = tid & 31;
    const int g    = lane >> 2;
    const int tig  = lane & 3;
    const int wm   = (warp >> 2) * 64;   // 0,64,128,192
    const int wn   = (warp & 3) * 32;    // 0,32,64,96
    const int bn   = blockIdx.x * 128;

    float acc[4][4][4];
#pragma unroll
    for (int i = 0; i < 4; ++i)
#pragma unroll
        for (int j = 0; j < 4; ++j)
#pragma unroll
            for (int r = 0; r < 4; ++r) acc[i][j][r] = 0.f;

    auto load_tile = [&](int t) {
        const int st = t & (S - 1);
        const int k0 = t * BK;
#pragma unroll
        for (int i = 0; i < 2; ++i) {   // A: 256 rows x 4 chunks of 16B
            int ch = tid + i * 512;
            int row = ch >> 2, c = ch & 3;
            cp16(sA + st * ASTG + row * AP + c * 8,
                 A + (size_t)row * NH2 + k0 + c * 8, true);
        }
#pragma unroll
        for (int i = 0; i < 2; ++i) {   // B: 32 rows x 32 chunks of 16B
            int ch = tid + i * 512;
            int r = ch >> 5, c = ch & 31;
            int col = bn + c * 4;
            bool v = col < NISO;
            cp16(sB + st * BSTG + r * BNP + c * 4,
                 W + (size_t)(k0 + r) * NISO + (v ? col : 0), v);
        }
        asm volatile("cp.async.commit_group;\n" ::: "memory");
    };

    load_tile(0); load_tile(1); load_tile(2);

    for (int t = 0; t < TK; ++t) {
        asm volatile("cp.async.wait_group 2;\n" ::: "memory");
        __syncthreads();

        if (t + 3 < TK) load_tile(t + 3);
        else asm volatile("cp.async.commit_group;\n" ::: "memory");

        const int st = t & (S - 1);
        const __half* a = sA + st * ASTG;
        const float*  b = sB + st * BSTG;

#pragma unroll
        for (int ks = 0; ks < 2; ++ks) {
            uint32_t af[4][4];
#pragma unroll
            for (int mt = 0; mt < 4; ++mt) {
                const uint32_t* ap0 = (const uint32_t*)(a + (wm + mt * 16 + g) * AP) + ks * 8;
                const uint32_t* ap1 = (const uint32_t*)(a + (wm + mt * 16 + g + 8) * AP) + ks * 8;
                af[mt][0] = ap0[tig];
                af[mt][1] = ap1[tig];
                af[mt][2] = ap0[tig + 4];
                af[mt][3] = ap1[tig + 4];
            }
            uint32_t bf[4][2];
#pragma unroll
            for (int nt = 0; nt < 4; ++nt) {
                const float* bp = b + (size_t)ks * 16 * BNP + wn + nt * 8 + g;
                float f0 = bp[(2 * tig) * BNP];
                float f1 = bp[(2 * tig + 1) * BNP];
                float f2 = bp[(2 * tig + 8) * BNP];
                float f3 = bp[(2 * tig + 9) * BNP];
                bf[nt][0] = pack_f16(f0, f1);
                bf[nt][1] = pack_f16(f2, f3);
            }
#pragma unroll
            for (int mt = 0; mt < 4; ++mt)
#pragma unroll
                for (int nt = 0; nt < 4; ++nt)
                    mma_f16(acc[mt][nt], af[mt], bf[nt]);
        }
    }

    __syncthreads();   // compute done; reuse smem

    // ---- single-pass epilogue: stage exp(logit+bias) for all 256 rows ----
#pragma unroll
    for (int nt = 0; nt < 4; ++nt) {
        int cl0  = wn + nt * 8 + tig * 2;
        int col0 = bn + cl0;
        float bia0 = (col0 < NISO)     ? bias[col0]     : 0.f;
        float bia1 = (col0 + 1 < NISO) ? bias[col0 + 1] : 0.f;
#pragma unroll
        for (int mt = 0; mt < 4; ++mt) {
            int rl = wm + mt * 16 + g;
#pragma unroll
            for (int r = 0; r < 4; ++r) {
                int rr  = rl + ((r >= 2) ? 8 : 0);
                int cl  = cl0 + (r & 1);
                int col = col0 + (r & 1);
                if (col < NISO)
                    sEp[rr * BNP + cl] =
                        __expf(acc[mt][nt][r] + ((r & 1) ? bia1 : bia0));
            }
        }
    }
    __syncthreads();

    // (a) denom red.v4: 128 cols x 256 rows (64 v4-groups per col, 16 per thread)
    {
        int c  = tid & 127;
        int rq = tid >> 7;               // 0..3
        int col = bn + c;
        if (col < NISO) {
            int gene = idx[col];
            float* dst = denom2 + (size_t)gene * NB;
#pragma unroll
            for (int p = 0; p < 16; ++p) {
                int r = (p * 4 + rq) * 4;
                float v0 = sEp[(r + 0) * BNP + c];
                float v1 = sEp[(r + 1) * BNP + c];
                float v2 = sEp[(r + 2) * BNP + c];
                float v3 = sEp[(r + 3) * BNP + c];
                asm volatile("red.global.add.v4.f32 [%0], {%1, %2, %3, %4};"
                             :: "l"(dst + r), "f"(v0), "f"(v1), "f"(v2), "f"(v3)
                             : "memory");
            }
        }
    }
    // (b) coalesced fp16 numerator stores: 256 rows x 32 groups of 4 cols (8B)
#pragma unroll
    for (int i = 0; i < 16; ++i) {
        int id = tid + i * 512;
        int rr = id >> 5, c4 = id & 31;
        int col = bn + c4 * 4;
        if (col < NISO) {
            float4 v = *(const float4*)&sEp[rr * BNP + c4 * 4];
            uint2 u;
            u.x = pack_f16(v.x, v.y);
            u.y = pack_f16(v.z, v.w);
            *(uint2*)&expH[(size_t)rr * NISO + col] = u;
        }
    }
}

// ================= Layers 1 & 2: fp16 GEMM (templated BK) =================
template<int BM, int BN, int WM, int WN, int BK>
__global__ void __launch_bounds__(256)
gemm_fp16_l12_kernel(const float* __restrict__ A, const float* __restrict__ W,
                     const float* __restrict__ bias, float* __restrict__ out,
                     int M, int N, int K)
{
    constexpr int S   = 3;
    constexpr int BKP = BK + 4;
    constexpr int BNP = BN + 4;
    constexpr int WARPS_N = BN / WN;
    constexpr int MT  = WM / 16;
    constexpr int NT  = WN / 8;
    constexpr int KS  = BK / 16;
    constexpr int ACH = BM * BK / 4;
    constexpr int BCH = BK * BN / 4;
    constexpr int AKC = BK / 4;       // 16B chunks per A row

    extern __shared__ float smem12[];
    float* sAb = smem12;
    float* sBb = smem12 + S * BM * BKP;

    const int tid  = threadIdx.x;
    const int warp = tid >> 5;
    const int lane = tid & 31;
    const int gid  = lane >> 2;
    const int tig  = lane & 3;
    const int wm   = (warp / WARPS_N) * WM;
    const int wn   = (warp % WARPS_N) * WN;
    const int bm   = blockIdx.y * BM;
    const int bn   = blockIdx.x * BN;

    const int T = (K + BK - 1) / BK;

    float acc[MT][NT][4];
#pragma unroll
    for (int i = 0; i < MT; ++i)
#pragma unroll
        for (int j = 0; j < NT; ++j)
#pragma unroll
            for (int r = 0; r < 4; ++r) acc[i][j][r] = 0.f;

    auto load_tile = [&](int t, int stage) {
        const int k0 = t * BK;
        float* sa = sAb + stage * BM * BKP;
        float* sb = sBb + stage * BK * BNP;
#pragma unroll
        for (int i = 0; i < (ACH + 255) / 256; ++i) {
            int c = tid + i * 256;
            if (ACH % 256 == 0 || c < ACH) {
                int row = c / AKC;
                int cc  = c % AKC;
                int kk  = k0 + cc * 4;
                int kc  = kk < K ? kk : 0;
                cp16(sa + row * BKP + cc * 4, A + (size_t)(bm + row) * K + kc, kk < K);
            }
        }
#pragma unroll
        for (int i = 0; i < (BCH + 255) / 256; ++i) {
            int c = tid + i * 256;
            if (BCH % 256 == 0 || c < BCH) {
                int row = c / (BN / 4);
                int cc  = c % (BN / 4);
                int col = bn + cc * 4;
                int kk  = k0 + row;
                bool p  = (kk < K) && (col < N);
                int kc  = kk < K ? kk : 0;
                int cl  = col < N ? col : 0;
                cp16(sb + row * BNP + cc * 4, W + (size_t)kc * N + cl, p);
            }
        }
        asm volatile("cp.async.commit_group;\n" ::: "memory");
    };

    load_tile(0, 0);
    if (T > 1) load_tile(1, 1); else asm volatile("cp.async.commit_group;\n" ::: "memory");

    for (int t = 0; t < T; ++t) {
        asm volatile("cp.async.wait_group 1;\n" ::: "memory");
        __syncthreads();
        if (t + 2 < T) load_tile(t + 2, (t + 2) % S);
        else asm volatile("cp.async.commit_group;\n" ::: "memory");

        const float* a = sAb + (t % S) * BM * BKP;
        const float* b = sBb + (t % S) * BK * BNP;

#pragma unroll
        for (int ksb = 0; ksb < KS; ++ksb) {
            uint32_t ah[MT][4];
#pragma unroll
            for (int mt = 0; mt < MT; ++mt) {
                const float* ap0 = a + (size_t)(wm + mt * 16 + gid) * BKP + ksb * 16;
                const float* ap1 = ap0 + 8 * BKP;
                float2 x0 = *(const float2*)(ap0 + 2 * tig);
                float2 x1 = *(const float2*)(ap1 + 2 * tig);
                float2 x2 = *(const float2*)(ap0 + 2 * tig + 8);
                float2 x3 = *(const float2*)(ap1 + 2 * tig + 8);
                ah[mt][0] = pack_f16(x0.x, x0.y);
                ah[mt][1] = pack_f16(x1.x, x1.y);
                ah[mt][2] = pack_f16(x2.x, x2.y);
                ah[mt][3] = pack_f16(x3.x, x3.y);
            }
            uint32_t bh[NT][2];
#pragma unroll
            for (int nt = 0; nt < NT; ++nt) {
                const float* bp = b + (size_t)ksb * 16 * BNP + wn + nt * 8 + gid;
                float f0 = bp[(2 * tig) * BNP];
                float f1 = bp[(2 * tig + 1) * BNP];
                float f2 = bp[(2 * tig + 8) * BNP];
                float f3 = bp[(2 * tig + 9) * BNP];
                bh[nt][0] = pack_f16(f0, f1);
                bh[nt][1] = pack_f16(f2, f3);
            }
#pragma unroll
            for (int mt = 0; mt < MT; ++mt)
#pragma unroll
                for (int nt = 0; nt < NT; ++nt)
                    mma_f16(acc[mt][nt], ah[mt], bh[nt]);
        }
    }

#pragma unroll
    for (int nt = 0; nt < NT; ++nt) {
        int col0 = bn + wn + nt * 8 + tig * 2;
        float bia0 = (col0 < N)     ? bias[col0]     : 0.f;
        float bia1 = (col0 + 1 < N) ? bias[col0 + 1] : 0.f;
#pragma unroll
        for (int mt = 0; mt < MT; ++mt) {
            int row0 = bm + wm + mt * 16 + gid;
#pragma unroll
            for (int r = 0; r < 4; ++r) {
                int row = row0 + ((r >= 2) ? 8 : 0);
                int col = col0 + (r & 1);
                if (col < N)
                    out[(size_t)row * N + col] = acc[mt][nt][r] + ((r & 1) ? bia1 : bia0);
            }
        }
    }
}

// ---------------- LayerNorm + exact GELU, 512 threads, float4-vectorized ----------------
template<typename OutT, bool ZERO>
__global__ void __launch_bounds__(512)
ln_gelu_kernel(const float* __restrict__ in, OutT* __restrict__ outp,
               const float* __restrict__ g,
               const float* __restrict__ beta, int H,
               float* __restrict__ zbuf)
{
    int row = blockIdx.x;
    if (ZERO) {
        float4* z = (float4*)(zbuf + (size_t)row * NG);
        for (int i = threadIdx.x; i < NG / 4; i += blockDim.x)
            z[i] = make_float4(0.f, 0.f, 0.f, 0.f);
    }
    const float4* x4 = (const float4*)(in + (size_t)row * H);
    const int H4 = H / 4;
    float s = 0.f, ss = 0.f;
    for (int i = threadIdx.x; i < H4; i += 512) {
        float4 v = x4[i];
        s  += v.x + v.y + v.z + v.w;
        ss += v.x * v.x + v.y * v.y + v.z * v.z + v.w * v.w;
    }
    __shared__ float sh[2][16];
#pragma unroll
    for (int o = 16; o > 0; o >>= 1) {
        s  += __shfl_xor_sync(0xffffffffu, s, o);
        ss += __shfl_xor_sync(0xffffffffu, ss, o);
    }
    int w = threadIdx.x >> 5;
    if ((threadIdx.x & 31) == 0) { sh[0][w] = s; sh[1][w] = ss; }
    __syncthreads();
    float ts = 0.f, tss = 0.f;
#pragma unroll
    for (int i = 0; i < 16; ++i) { ts += sh[0][i]; tss += sh[1][i]; }
    float mu   = ts / (float)H;
    float var  = tss / (float)H - mu * mu;
    float rstd = rsqrtf(var + 1e-5f);
    const float4* g4  = (const float4*)g;
    const float4* be4 = (const float4*)beta;
    for (int i = threadIdx.x; i < H4; i += 512) {
        float4 v = x4[i];
        float4 gg = g4[i];
        float4 bb = be4[i];
        float o0 = (v.x - mu) * rstd * gg.x + bb.x;
        float o1 = (v.y - mu) * rstd * gg.y + bb.y;
        float o2 = (v.z - mu) * rstd * gg.z + bb.z;
        float o3 = (v.w - mu) * rstd * gg.w + bb.w;
        o0 = 0.5f * o0 * (1.0f + erff(o0 * 0.70710678118654752f));
        o1 = 0.5f * o1 * (1.0f + erff(o1 * 0.70710678118654752f));
        o2 = 0.5f * o2 * (1.0f + erff(o2 * 0.70710678118654752f));
        o3 = 0.5f * o3 * (1.0f + erff(o3 * 0.70710678118654752f));
        if constexpr (sizeof(OutT) == 2) {
            uint2 u;
            u.x = pack_f16(o0, o1);
            u.y = pack_f16(o2, o3);
            *(uint2*)&outp[(size_t)row * H + i * 4] = u;
        } else {
            *(float4*)&outp[(size_t)row * H + i * 4] = make_float4(o0, o1, o2, o3);
        }
    }
}

// ---------------- denom transpose: [gene][batch] -> [batch][gene] ----------------
__global__ void transpose_kernel(const float* __restrict__ in, float* __restrict__ out)
{
    __shared__ float t[32][33];
    int g0 = blockIdx.x * 32, b0 = blockIdx.y * 32;
#pragma unroll
    for (int dy = 0; dy < 32; dy += 8) {
        int gg = g0 + threadIdx.y + dy;
        if (gg < NG) t[threadIdx.y + dy][threadIdx.x] = in[(size_t)gg * NB + b0 + threadIdx.x];
    }
    __syncthreads();
#pragma unroll
    for (int dy = 0; dy < 32; dy += 8) {
        int gg = g0 + threadIdx.x;
        int bb = b0 + threadIdx.y + dy;
        if (gg < NG) out[(size_t)bb * NG + gg] = t[threadIdx.x][threadIdx.y + dy];
    }
}

// ---------------- normalize: fp16 numerator * smem-resident reciprocal ----------------
__global__ void __launch_bounds__(512)
div_kernel(float* __restrict__ out, const __half* __restrict__ expH,
           const float* __restrict__ denomT, const int* __restrict__ idx)
{
    extern __shared__ float sd[];      // NG floats = 100 KB (reciprocals)
    int b = blockIdx.x;
    const float4* dr = (const float4*)(denomT + (size_t)b * NG);
    for (int i = threadIdx.x; i < NG / 4; i += blockDim.x) {
        float4 d = dr[i];
        float4 rc;
        rc.x = 1.0f / fmaxf(d.x, 1e-8f);
        rc.y = 1.0f / fmaxf(d.y, 1e-8f);
        rc.z = 1.0f / fmaxf(d.z, 1e-8f);
        rc.w = 1.0f / fmaxf(d.w, 1e-8f);
        ((float4*)sd)[i] = rc;
    }
    __syncthreads();
    float4* orow = (float4*)(out + (size_t)b * NISO);
    const uint2* erow = (const uint2*)(expH + (size_t)b * NISO);
    const int4* gi = (const int4*)idx;
    for (int i = threadIdx.x; i < NISO / 4; i += blockDim.x) {
        uint2 u = erow[i];
        float2 e01 = __half22float2(*(const __half2*)&u.x);
        float2 e23 = __half22float2(*(const __half2*)&u.y);
        int4 g4 = gi[i];
        float4 v;
        v.x = e01.x * sd[g4.x];
        v.y = e01.y * sd[g4.y];
        v.z = e23.x * sd[g4.z];
        v.w = e23.y * sd[g4.w];
        orow[i] = v;
    }
}

extern "C" void kernel_launch(void* const* d_in, const int* in_sizes, int n_in,
                              void* d_out, int out_size)
{
    const float* x   = (const float*)d_in[0];
    const int*   idx = (const int*)  d_in[1];
    const float* W1  = (const float*)d_in[2];
    const float* b1  = (const float*)d_in[3];
    const float* g1  = (const float*)d_in[4];
    const float* be1 = (const float*)d_in[5];
    const float* W2  = (const float*)d_in[6];
    const float* b2  = (const float*)d_in[7];
    const float* g2  = (const float*)d_in[8];
    const float* be2 = (const float*)d_in[9];
    const float* W3  = (const float*)d_in[10];
    const float* b3  = (const float*)d_in[11];
    float* out = (float*)d_out;

    float *h1, *h2, *denom2, *denomT;
    __half *h2h, *exph;
    cudaGetSymbolAddress((void**)&h1, g_h1);
    cudaGetSymbolAddress((void**)&h2, g_h2);
    cudaGetSymbolAddress((void**)&h2h, g_h2h);
    cudaGetSymbolAddress((void**)&denom2, g_denom2);
    cudaGetSymbolAddress((void**)&denomT, g_denomT);
    cudaGetSymbolAddress((void**)&exph, g_exph);

    // ---- Layer 1: x @ W1 (fp16, BK=32 -> 157 iters), 256 CTAs ----
    {
        constexpr int BM = 32, BN = 64, BK = 32;
        constexpr int SM = 3 * (BM * (BK + 4) + BK * (BN + 4)) * 4;
        auto k = gemm_fp16_l12_kernel<BM, BN, 16, 16, BK>;
        cudaFuncSetAttribute(k, cudaFuncAttributeMaxDynamicSharedMemorySize, SM);
        dim3 grid(NH1 / BN, NB / BM);
        k<<<grid, 256, SM>>>(x, W1, b1, h1, NB, NH1, DIN);
    }
    ln_gelu_kernel<float, false><<<NB, 512>>>(h1, h1, g1, be1, NH1, nullptr);

    // ---- Layer 2: h1 @ W2 (fp16, BK=32 -> 64 iters) ----
    {
        constexpr int BM = 32, BN = 64, BK = 32;
        constexpr int SM = 3 * (BM * (BK + 4) + BK * (BN + 4)) * 4;
        auto k = gemm_fp16_l12_kernel<BM, BN, 16, 16, BK>;
        cudaFuncSetAttribute(k, cudaFuncAttributeMaxDynamicSharedMemorySize, SM);
        dim3 grid(NH2 / BN, NB / BM);
        k<<<grid, 256, SM>>>(h1, W2, b2, h2, NB, NH2, NH1);
    }
    // LN2 also zeros denom2
    ln_gelu_kernel<__half, true><<<NB, 512>>>(h2, h2h, g2, be2, NH2, denom2);

    // ---- Layer 3: fp16 mma GEMM, BM=256 x BN=128, BK=32, single-pass epilogue ----
    {
        constexpr int ASTG = 256 * 40;            // halfs
        constexpr int BSTG = 32 * 132;            // floats
        constexpr int SM3  = 4 * (ASTG * 2 + BSTG * 4);  // 149504 B
        cudaFuncSetAttribute(gemm3_fp16_kernel, cudaFuncAttributeMaxDynamicSharedMemorySize, SM3);
        gemm3_fp16_kernel<<<(NISO + 127) / 128, 512, SM3>>>(h2h, W3, b3, idx, exph, denom2);
    }

    // ---- transpose denom, then normalize fp16 numerators with reciprocal rows ----
    {
        dim3 grid((NG + 31) / 32, NB / 32);
        transpose_kernel<<<grid, dim3(32, 8)>>>(denom2, denomT);

        constexpr int SMD = NG * 4;  // 100 KB
        cudaFuncSetAttribute(div_kernel, cudaFuncAttributeMaxDynamicSharedMemorySize, SMD);
        div_kernel<<<NB, 512, SMD>>>(out, exph, denomT, idx);
    }
}